// round 1
// baseline (speedup 1.0000x reference)
#include <cuda_runtime.h>
#include <math.h>

// ---------------------------------------------------------------------------
// NanoGPT forward (B=4, T=1024, E=1024, H=16, L=6, V=50257), fp32 baseline.
// ---------------------------------------------------------------------------

#define NB     4
#define NT     1024
#define NE     1024
#define NH     16
#define HDIM   64
#define NLAYER 6
#define NV     50257
#define NM     (NB * NT)       // 4096 rows
#define LN_EPS 1e-5f

// ------------------------------- scratch -----------------------------------
__device__ float g_x  [NM * NE];                        // residual stream (16MB)
__device__ float g_h  [NM * NE];                        // layernorm out   (16MB)
__device__ float g_qkv[NM * 3 * NE];                    // qkv             (48MB)
__device__ float g_y  [NM * NE];                        // attn out        (16MB)
__device__ float g_fc [NM * 4 * NE];                    // mlp hidden      (64MB)
__device__ float g_att[(size_t)NB * NH * NT * NT];      // scores / logits chunk (256MB)
__device__ float g_nll[NM];

// ------------------------------- embed -------------------------------------
__global__ void embed_kernel(const int* __restrict__ idx,
                             const float* __restrict__ wte,
                             const float* __restrict__ wpe) {
    int row = blockIdx.x;
    int t   = row % NT;
    int tok = idx[row];
    const float* s = wte + (size_t)tok * NE;
    const float* p = wpe + (size_t)t * NE;
    float* o = g_x + (size_t)row * NE;
    for (int c = threadIdx.x; c < NE; c += blockDim.x)
        o[c] = s[c] + p[c];
}

// ------------------------------ layernorm -----------------------------------
__global__ void ln_kernel(const float* __restrict__ in,
                          const float* __restrict__ w,
                          const float* __restrict__ b,
                          float* __restrict__ out) {
    int row = blockIdx.x;
    int tid = threadIdx.x;
    const float* x = in + (size_t)row * NE;
    float* o = out + (size_t)row * NE;
    __shared__ float red[256];
    __shared__ float s_mu, s_rstd;

    float s = 0.f;
    for (int c = tid; c < NE; c += 256) s += x[c];
    red[tid] = s; __syncthreads();
    for (int o2 = 128; o2 > 0; o2 >>= 1) {
        if (tid < o2) red[tid] += red[tid + o2];
        __syncthreads();
    }
    if (tid == 0) s_mu = red[0] * (1.0f / NE);
    __syncthreads();
    float mu = s_mu;

    float v = 0.f;
    for (int c = tid; c < NE; c += 256) { float d = x[c] - mu; v += d * d; }
    red[tid] = v; __syncthreads();
    for (int o2 = 128; o2 > 0; o2 >>= 1) {
        if (tid < o2) red[tid] += red[tid + o2];
        __syncthreads();
    }
    if (tid == 0) s_rstd = rsqrtf(red[0] * (1.0f / NE) + LN_EPS);
    __syncthreads();
    float rstd = s_rstd;

    for (int c = tid; c < NE; c += 256)
        o[c] = (x[c] - mu) * rstd * w[c] + b[c];
}

// ------------------------------- GEMM ---------------------------------------
// C[M,N] = A[M,K] * op(B)   (TRANSB: B is [N,K] row-major; else B is [K,N])
// EPI: 0 = store, 1 = gelu(store), 2 = C += acc (residual)
// Batched: z -> (zb = z/zdiv, zh = z%zdiv) offsets per operand.
#define BM 64
#define BN 64
#define BK 16

__device__ __forceinline__ float gelu_f(float x) {
    return 0.5f * x * (1.0f + erff(x * 0.70710678118654752f));
}

template <bool TRANSB, int EPI>
__global__ void __launch_bounds__(256)
gemm_kernel(const float* __restrict__ A, const float* __restrict__ B,
            float* __restrict__ C,
            int M, int N, int K, int lda, int ldb, int ldc,
            int zdiv,
            long long sAb, long long sAh,
            long long sBb, long long sBh,
            long long sCb, long long sCh) {
    int z = blockIdx.z;
    int zb = z / zdiv, zh = z % zdiv;
    A += zb * sAb + zh * sAh;
    B += zb * sBb + zh * sBh;
    C += zb * sCb + zh * sCh;

    int bm = blockIdx.y * BM;
    int bn = blockIdx.x * BN;
    int tid = threadIdx.x;
    int ty = tid >> 4;          // 0..15 -> rows
    int tx = tid & 15;          // 0..15 -> cols

    __shared__ float As[BK][BM + 4];
    __shared__ float Bs[BK][BN + 4];

    float acc[4][4];
#pragma unroll
    for (int i = 0; i < 4; i++)
#pragma unroll
        for (int j = 0; j < 4; j++) acc[i][j] = 0.f;

    for (int k0 = 0; k0 < K; k0 += BK) {
        // A tile: 64 x 16, one float4 per thread along K, store transposed
        {
            int m = tid >> 2;
            int kq = (tid & 3) << 2;
            float4 v = *(const float4*)(A + (size_t)(bm + m) * lda + k0 + kq);
            As[kq + 0][m] = v.x; As[kq + 1][m] = v.y;
            As[kq + 2][m] = v.z; As[kq + 3][m] = v.w;
        }
        if (TRANSB) {
            int n = tid >> 2;
            int kq = (tid & 3) << 2;
            float4 v = make_float4(0.f, 0.f, 0.f, 0.f);
            if (bn + n < N)
                v = *(const float4*)(B + (size_t)(bn + n) * ldb + k0 + kq);
            Bs[kq + 0][n] = v.x; Bs[kq + 1][n] = v.y;
            Bs[kq + 2][n] = v.z; Bs[kq + 3][n] = v.w;
        } else {
            int k = tid >> 4;
            int nq = (tid & 15) << 2;
            float4 v = *(const float4*)(B + (size_t)(k0 + k) * ldb + bn + nq);
            *(float4*)&Bs[k][nq] = v;
        }
        __syncthreads();

#pragma unroll
        for (int k = 0; k < BK; k++) {
            float4 a = *(const float4*)&As[k][ty << 2];
            float4 b = *(const float4*)&Bs[k][tx << 2];
            float ar[4] = {a.x, a.y, a.z, a.w};
            float br[4] = {b.x, b.y, b.z, b.w};
#pragma unroll
            for (int i = 0; i < 4; i++)
#pragma unroll
                for (int j = 0; j < 4; j++)
                    acc[i][j] += ar[i] * br[j];
        }
        __syncthreads();
    }

#pragma unroll
    for (int i = 0; i < 4; i++) {
        int row = bm + (ty << 2) + i;
        float* crow = C + (size_t)row * ldc;
#pragma unroll
        for (int j = 0; j < 4; j++) {
            int col = bn + (tx << 2) + j;
            if (col < N) {
                if (EPI == 0)      crow[col] = acc[i][j];
                else if (EPI == 1) crow[col] = gelu_f(acc[i][j]);
                else               crow[col] += acc[i][j];
            }
        }
    }
}

// ------------------------------ softmax -------------------------------------
__global__ void softmax_kernel() {
    int q  = blockIdx.x;
    int bh = blockIdx.y;
    float* s = g_att + (size_t)bh * NT * NT + (size_t)q * NT;
    int len = q + 1;
    const float scale = 0.125f;   // 1/sqrt(64)
    int tid = threadIdx.x;
    __shared__ float red[128];

    float m = -1e30f;
    for (int j = tid; j < len; j += 128) m = fmaxf(m, s[j] * scale);
    red[tid] = m; __syncthreads();
    for (int o = 64; o > 0; o >>= 1) {
        if (tid < o) red[tid] = fmaxf(red[tid], red[tid + o]);
        __syncthreads();
    }
    m = red[0]; __syncthreads();

    float sum = 0.f;
    for (int j = tid; j < len; j += 128) sum += expf(s[j] * scale - m);
    red[tid] = sum; __syncthreads();
    for (int o = 64; o > 0; o >>= 1) {
        if (tid < o) red[tid] += red[tid + o];
        __syncthreads();
    }
    float inv = 1.0f / red[0];

    for (int j = tid; j < NT; j += 128)
        s[j] = (j < len) ? expf(s[j] * scale - m) * inv : 0.f;
}

// ------------------------------- loss ---------------------------------------
__global__ void loss_row_kernel(const float* __restrict__ logits,
                                const int* __restrict__ targets,
                                int row0, int ldl) {
    int r = blockIdx.x;
    int tid = threadIdx.x;
    const float* L = logits + (size_t)r * ldl;
    float m = -1e30f, sacc = 0.f;
    for (int j = tid; j < NV; j += 256) {
        float v = L[j];
        if (v > m) { sacc = sacc * expf(m - v) + 1.0f; m = v; }
        else       { sacc += expf(v - m); }
    }
    __shared__ float sm[256], ss[256];
    sm[tid] = m; ss[tid] = sacc; __syncthreads();
    for (int o = 128; o > 0; o >>= 1) {
        if (tid < o) {
            float m2 = sm[tid + o], s2 = ss[tid + o];
            float M  = fmaxf(sm[tid], m2);
            ss[tid]  = ss[tid] * expf(sm[tid] - M) + s2 * expf(m2 - M);
            sm[tid]  = M;
        }
        __syncthreads();
    }
    if (tid == 0) {
        int grow = row0 + r;
        int tgt = targets[grow];
        float nll = 0.f;
        if (tgt != -1) nll = sm[0] + logf(ss[0]) - L[tgt];
        g_nll[grow] = nll;
    }
}

__global__ void loss_reduce_kernel(const int* __restrict__ targets,
                                   float* __restrict__ out) {
    int tid = threadIdx.x;
    __shared__ float ssum[256];
    __shared__ int scnt[256];
    float s = 0.f; int c = 0;
    for (int r = tid; r < NM; r += 256)
        if (targets[r] != -1) { s += g_nll[r]; c++; }
    ssum[tid] = s; scnt[tid] = c; __syncthreads();
    for (int o = 128; o > 0; o >>= 1) {
        if (tid < o) { ssum[tid] += ssum[tid + o]; scnt[tid] += scnt[tid + o]; }
        __syncthreads();
    }
    if (tid == 0) out[0] = ssum[0] / (float)max(scnt[0], 1);
}

// ------------------------------- host ---------------------------------------
template <bool TB, int EPI>
static void launch_gemm(const float* A, const float* B, float* C,
                        int M, int N, int K, int lda, int ldb, int ldc,
                        int batch = 1, int zdiv = 1,
                        long long sAb = 0, long long sAh = 0,
                        long long sBb = 0, long long sBh = 0,
                        long long sCb = 0, long long sCh = 0) {
    dim3 grid((N + BN - 1) / BN, (M + BM - 1) / BM, batch);
    gemm_kernel<TB, EPI><<<grid, 256>>>(A, B, C, M, N, K, lda, ldb, ldc,
                                        zdiv, sAb, sAh, sBb, sBh, sCb, sCh);
}

extern "C" void kernel_launch(void* const* d_in, const int* in_sizes, int n_in,
                              void* d_out, int out_size) {
    const int*   idx      = (const int*)  d_in[0];
    const int*   targets  = (const int*)  d_in[1];
    const float* wte      = (const float*)d_in[2];
    const float* wpe      = (const float*)d_in[3];
    const float* ln1_w    = (const float*)d_in[4];
    const float* ln1_b    = (const float*)d_in[5];
    const float* attn_w   = (const float*)d_in[6];
    const float* attn_pw  = (const float*)d_in[7];
    const float* ln2_w    = (const float*)d_in[8];
    const float* ln2_b    = (const float*)d_in[9];
    const float* fc_w     = (const float*)d_in[10];
    const float* fc_pw    = (const float*)d_in[11];
    const float* lnf_w    = (const float*)d_in[12];
    const float* lnf_b    = (const float*)d_in[13];
    const float* lm_w     = (const float*)d_in[14];

    float *x, *h, *qkv, *y, *fc, *att;
    cudaGetSymbolAddress((void**)&x,   g_x);
    cudaGetSymbolAddress((void**)&h,   g_h);
    cudaGetSymbolAddress((void**)&qkv, g_qkv);
    cudaGetSymbolAddress((void**)&y,   g_y);
    cudaGetSymbolAddress((void**)&fc,  g_fc);
    cudaGetSymbolAddress((void**)&att, g_att);

    embed_kernel<<<NM, 256>>>(idx, wte, wpe);

    const long long sQKVb = (long long)NT * 3 * NE;   // per-batch stride in qkv
    const long long sAttB = (long long)NH * NT * NT;
    const long long sAttH = (long long)NT * NT;

    for (int i = 0; i < NLAYER; i++) {
        const float* aw  = attn_w  + (size_t)i * 3 * NE * NE;
        const float* pw  = attn_pw + (size_t)i * NE * NE;
        const float* fw  = fc_w    + (size_t)i * 4 * NE * NE;
        const float* fpw = fc_pw   + (size_t)i * NE * 4 * NE;

        // ln1
        ln_kernel<<<NM, 256>>>(x, ln1_w + i * NE, ln1_b + i * NE, h);
        // qkv = h @ attn_w^T   (4096 x 3072 x 1024)
        launch_gemm<true, 0>(h, aw, qkv, NM, 3 * NE, NE, NE, NE, 3 * NE);
        // S = Q @ K^T, batched over (b,h)
        launch_gemm<true, 0>(qkv, qkv + NE, att,
                             NT, NT, HDIM, 3 * NE, 3 * NE, NT,
                             NB * NH, NH,
                             sQKVb, 64, sQKVb, 64, sAttB, sAttH);
        // causal softmax (scale inside)
        softmax_kernel<<<dim3(NT, NB * NH), 128>>>();
        // Y = P @ V
        launch_gemm<false, 0>(att, qkv + 2 * NE, y,
                              NT, HDIM, NT, NT, 3 * NE, NE,
                              NB * NH, NH,
                              sAttB, sAttH, sQKVb, 64, (long long)NT * NE, 64);
        // x += y @ attn_proj_w^T
        launch_gemm<true, 2>(y, pw, x, NM, NE, NE, NE, NE, NE);
        // ln2
        ln_kernel<<<NM, 256>>>(x, ln2_w + i * NE, ln2_b + i * NE, h);
        // fc = gelu(h @ fc_w^T)   (4096 x 4096 x 1024)
        launch_gemm<true, 1>(h, fw, fc, NM, 4 * NE, NE, NE, NE, 4 * NE);
        // x += fc @ fc_proj_w^T   (4096 x 1024 x 4096)
        launch_gemm<true, 2>(fc, fpw, x, NM, NE, 4 * NE, 4 * NE, 4 * NE, NE);
    }

    // final layernorm
    ln_kernel<<<NM, 256>>>(x, lnf_w, lnf_b, h);

    const size_t P = (size_t)NM * NV;   // logits element count
    float* out = (float*)d_out;

    if ((size_t)out_size >= P) {
        // logits straight into d_out
        launch_gemm<true, 0>(h, lm_w, out, NM, NV, NE, NE, NE, NV);
        loss_row_kernel<<<NM, 256>>>(out, targets, 0, NV);
        if ((size_t)out_size >= P + 1)
            loss_reduce_kernel<<<1, 256>>>(targets, out + P);
    } else {
        // loss-only output: chunk logits through the attention scratch
        const int CHUNK = 1024;
        for (int c = 0; c < NM / CHUNK; c++) {
            launch_gemm<true, 0>(h + (size_t)c * CHUNK * NE, lm_w, att,
                                 CHUNK, NV, NE, NE, NE, NV);
            loss_row_kernel<<<CHUNK, 256>>>(att, targets, c * CHUNK, NV);
        }
        int li = (out_size >= 1) ? out_size - 1 : 0;
        loss_reduce_kernel<<<1, 256>>>(targets, out + li);
    }
}

// round 2
// speedup vs baseline: 1.9172x; 1.9172x over previous
#include <cuda_runtime.h>
#include <math.h>

// ---------------------------------------------------------------------------
// NanoGPT forward (B=4, T=1024, E=1024, H=16, L=6, V=50257)
// R2: all GEMMs on tensor cores via tf32 mma.sync.m16n8k8 (fp32 accumulate).
// ---------------------------------------------------------------------------

#define NB     4
#define NT     1024
#define NE     1024
#define NH     16
#define HDIM   64
#define NLAYER 6
#define NV     50257
#define NM     (NB * NT)       // 4096 rows
#define LN_EPS 1e-5f

// ------------------------------- scratch -----------------------------------
__device__ float g_x  [NM * NE];                        // residual stream (16MB)
__device__ float g_h  [NM * NE];                        // layernorm out   (16MB)
__device__ float g_qkv[NM * 3 * NE];                    // qkv             (48MB)
__device__ float g_y  [NM * NE];                        // attn out        (16MB)
__device__ float g_fc [NM * 4 * NE];                    // mlp hidden      (64MB)
__device__ float g_vt [NB * NH * HDIM * NT];            // V transposed    (16MB)
__device__ float g_att[(size_t)NB * NH * NT * NT];      // scores / logits chunk (256MB)
__device__ float g_nll[NM];

// ------------------------------- embed -------------------------------------
__global__ void embed_kernel(const int* __restrict__ idx,
                             const float* __restrict__ wte,
                             const float* __restrict__ wpe) {
    int row = blockIdx.x;
    int t   = row % NT;
    int tok = idx[row];
    const float* s = wte + (size_t)tok * NE;
    const float* p = wpe + (size_t)t * NE;
    float* o = g_x + (size_t)row * NE;
    for (int c = threadIdx.x; c < NE; c += blockDim.x)
        o[c] = s[c] + p[c];
}

// ------------------------------ layernorm -----------------------------------
__global__ void ln_kernel(const float* __restrict__ in,
                          const float* __restrict__ w,
                          const float* __restrict__ b,
                          float* __restrict__ out) {
    int row = blockIdx.x;
    int tid = threadIdx.x;
    const float* x = in + (size_t)row * NE;
    float* o = out + (size_t)row * NE;
    __shared__ float red[256];
    __shared__ float s_mu, s_rstd;

    float s = 0.f;
    for (int c = tid; c < NE; c += 256) s += x[c];
    red[tid] = s; __syncthreads();
    for (int o2 = 128; o2 > 0; o2 >>= 1) {
        if (tid < o2) red[tid] += red[tid + o2];
        __syncthreads();
    }
    if (tid == 0) s_mu = red[0] * (1.0f / NE);
    __syncthreads();
    float mu = s_mu;

    float v = 0.f;
    for (int c = tid; c < NE; c += 256) { float d = x[c] - mu; v += d * d; }
    red[tid] = v; __syncthreads();
    for (int o2 = 128; o2 > 0; o2 >>= 1) {
        if (tid < o2) red[tid] += red[tid + o2];
        __syncthreads();
    }
    if (tid == 0) s_rstd = rsqrtf(red[0] * (1.0f / NE) + LN_EPS);
    __syncthreads();
    float rstd = s_rstd;

    for (int c = tid; c < NE; c += 256)
        o[c] = (x[c] - mu) * rstd * w[c] + b[c];
}

// ------------------------- tf32 tensor-core GEMM -----------------------------
// C[M,N] = A[M,K] * B^T   (B stored [N,K] row-major)
// EPI: 0 = store, 1 = gelu(store), 2 = C += acc (residual)
// Block tile 128x128x32, 256 threads (8 warps = 2m x 4n), warp tile 64x32.
// Requirements: M % 128 == 0, K % 32 == 0 (true for all call sites).

__device__ __forceinline__ unsigned f2tf(float f) {
    unsigned u;
    asm("cvt.rna.tf32.f32 %0, %1;" : "=r"(u) : "f"(f));
    return u;
}

__device__ __forceinline__ void mma8(float* c, const unsigned* a, const unsigned* b) {
    asm volatile(
        "mma.sync.aligned.m16n8k8.row.col.f32.tf32.tf32.f32 "
        "{%0,%1,%2,%3}, {%4,%5,%6,%7}, {%8,%9}, {%0,%1,%2,%3};"
        : "+f"(c[0]), "+f"(c[1]), "+f"(c[2]), "+f"(c[3])
        : "r"(a[0]), "r"(a[1]), "r"(a[2]), "r"(a[3]),
          "r"(b[0]), "r"(b[1]));
}

__device__ __forceinline__ float gelu_f(float x) {
    return 0.5f * x * (1.0f + erff(x * 0.70710678118654752f));
}

#define TPAD 36                 // smem row stride (conflict-free fragment reads)
#define TILE_U (128 * TPAD)     // 4608 unsigned per tile

template <int EPI>
__global__ void __launch_bounds__(256, 1)
mma_gemm(const float* __restrict__ A, const float* __restrict__ B,
         float* __restrict__ C,
         int M, int N, int K, int lda, int ldb, int ldc,
         int zdiv,
         long long sAb, long long sAh,
         long long sBb, long long sBh,
         long long sCb, long long sCh) {
    extern __shared__ unsigned sh[];
    int z = blockIdx.z;
    int zb = z / zdiv, zh = z % zdiv;
    A += zb * sAb + zh * sAh;
    B += zb * sBb + zh * sBh;
    C += zb * sCb + zh * sCh;

    const int bm   = blockIdx.y * 128;
    const int bn   = blockIdx.x * 128;
    const int tid  = threadIdx.x;
    const int lane = tid & 31;
    const int wid  = tid >> 5;
    const int wm   = (wid >> 2) * 64;   // warp m offset within block
    const int wn   = (wid & 3) * 32;    // warp n offset within block
    const int lr   = lane >> 2;         // groupID
    const int lc   = lane & 3;          // threadID in group

    // double-buffered tiles: [buf] { As[128][36] | Bs[128][36] }
    unsigned* AsBuf[2] = { sh,              sh + 2 * TILE_U };
    unsigned* BsBuf[2] = { sh + TILE_U,     sh + 3 * TILE_U };

    float acc[4][4][4];
#pragma unroll
    for (int i = 0; i < 4; i++)
#pragma unroll
        for (int j = 0; j < 4; j++)
#pragma unroll
            for (int q = 0; q < 4; q++) acc[i][j][q] = 0.f;

    uint4 ra[4], rb[4];

    // ---- stage k-tile 0 ----
#pragma unroll
    for (int i = 0; i < 4; i++) {
        int idx = tid + i * 256;
        int row = idx >> 3;
        int kq  = (idx & 7) << 2;
        float4 va = *(const float4*)(A + (size_t)(bm + row) * lda + kq);
        ra[i] = make_uint4(f2tf(va.x), f2tf(va.y), f2tf(va.z), f2tf(va.w));
        int n = bn + row;
        float4 vb = make_float4(0.f, 0.f, 0.f, 0.f);
        if (n < N) vb = *(const float4*)(B + (size_t)n * ldb + kq);
        rb[i] = make_uint4(f2tf(vb.x), f2tf(vb.y), f2tf(vb.z), f2tf(vb.w));
    }
#pragma unroll
    for (int i = 0; i < 4; i++) {
        int idx = tid + i * 256;
        int row = idx >> 3;
        int kq  = (idx & 7) << 2;
        *(uint4*)&AsBuf[0][row * TPAD + kq] = ra[i];
        *(uint4*)&BsBuf[0][row * TPAD + kq] = rb[i];
    }
    __syncthreads();

    const int KT = K >> 5;
    for (int kt = 0; kt < KT; kt++) {
        const int buf = kt & 1;
        const bool more = (kt + 1 < KT);
        if (more) {
            const int k0 = (kt + 1) << 5;
#pragma unroll
            for (int i = 0; i < 4; i++) {
                int idx = tid + i * 256;
                int row = idx >> 3;
                int kq  = (idx & 7) << 2;
                float4 va = *(const float4*)(A + (size_t)(bm + row) * lda + k0 + kq);
                ra[i] = make_uint4(f2tf(va.x), f2tf(va.y), f2tf(va.z), f2tf(va.w));
                int n = bn + row;
                float4 vb = make_float4(0.f, 0.f, 0.f, 0.f);
                if (n < N) vb = *(const float4*)(B + (size_t)n * ldb + k0 + kq);
                rb[i] = make_uint4(f2tf(vb.x), f2tf(vb.y), f2tf(vb.z), f2tf(vb.w));
            }
        }

        const unsigned* As = AsBuf[buf];
        const unsigned* Bs = BsBuf[buf];
#pragma unroll
        for (int ks = 0; ks < 4; ks++) {
            unsigned afr[4][4], bfr[4][2];
#pragma unroll
            for (int i = 0; i < 4; i++) {
                const unsigned* p = &As[(wm + i * 16 + lr) * TPAD + ks * 8 + lc];
                afr[i][0] = p[0];
                afr[i][1] = p[8 * TPAD];
                afr[i][2] = p[4];
                afr[i][3] = p[8 * TPAD + 4];
            }
#pragma unroll
            for (int j = 0; j < 4; j++) {
                const unsigned* p = &Bs[(wn + j * 8 + lr) * TPAD + ks * 8 + lc];
                bfr[j][0] = p[0];
                bfr[j][1] = p[4];
            }
#pragma unroll
            for (int i = 0; i < 4; i++)
#pragma unroll
                for (int j = 0; j < 4; j++)
                    mma8(acc[i][j], afr[i], bfr[j]);
        }

        if (more) {
            const int nb = buf ^ 1;
#pragma unroll
            for (int i = 0; i < 4; i++) {
                int idx = tid + i * 256;
                int row = idx >> 3;
                int kq  = (idx & 7) << 2;
                *(uint4*)&AsBuf[nb][row * TPAD + kq] = ra[i];
                *(uint4*)&BsBuf[nb][row * TPAD + kq] = rb[i];
            }
        }
        __syncthreads();
    }

    // ---- epilogue (scalar stores: ldc may be odd, e.g. 50257) ----
#pragma unroll
    for (int i = 0; i < 4; i++) {
        int r0 = bm + wm + i * 16 + lr;
        float* C0 = C + (size_t)r0 * ldc;
        float* C1 = C0 + (size_t)8 * ldc;
#pragma unroll
        for (int j = 0; j < 4; j++) {
            int c0 = bn + wn + j * 8 + (lc << 1);
            const float* a4 = acc[i][j];
#pragma unroll
            for (int q = 0; q < 2; q++) {
                int col = c0 + q;
                if (col < N) {
                    if (EPI == 0) {
                        C0[col] = a4[q];
                        C1[col] = a4[q + 2];
                    } else if (EPI == 1) {
                        C0[col] = gelu_f(a4[q]);
                        C1[col] = gelu_f(a4[q + 2]);
                    } else {
                        C0[col] += a4[q];
                        C1[col] += a4[q + 2];
                    }
                }
            }
        }
    }
}

// --------------------------- V transpose ------------------------------------
// g_vt[bh][d][t] = g_qkv[b][t][2*NE + h*64 + d]
__global__ void transpose_v_kernel() {
    __shared__ float tile[32][33];
    int bh = blockIdx.y;
    int b = bh >> 4, h = bh & 15;
    int t0 = blockIdx.x * 32;
    int tx = threadIdx.x, ty = threadIdx.y;     // 32 x 8
    const float* src = g_qkv + (size_t)b * NT * (3 * NE) + 2 * NE + h * 64;
    float* dst = g_vt + (size_t)bh * HDIM * NT;
    for (int d0 = 0; d0 < HDIM; d0 += 32) {
#pragma unroll
        for (int i = 0; i < 32; i += 8)
            tile[ty + i][tx] = src[(size_t)(t0 + ty + i) * (3 * NE) + d0 + tx];
        __syncthreads();
#pragma unroll
        for (int i = 0; i < 32; i += 8)
            dst[(size_t)(d0 + ty + i) * NT + t0 + tx] = tile[tx][ty + i];
        __syncthreads();
    }
}

// ------------------------------ softmax -------------------------------------
__global__ void softmax_kernel() {
    int q  = blockIdx.x;
    int bh = blockIdx.y;
    float* s = g_att + (size_t)bh * NT * NT + (size_t)q * NT;
    int len = q + 1;
    const float scale = 0.125f;   // 1/sqrt(64)
    int tid = threadIdx.x;
    __shared__ float red[128];

    float m = -1e30f;
    for (int j = tid; j < len; j += 128) m = fmaxf(m, s[j] * scale);
    red[tid] = m; __syncthreads();
    for (int o = 64; o > 0; o >>= 1) {
        if (tid < o) red[tid] = fmaxf(red[tid], red[tid + o]);
        __syncthreads();
    }
    m = red[0]; __syncthreads();

    float sum = 0.f;
    for (int j = tid; j < len; j += 128) sum += expf(s[j] * scale - m);
    red[tid] = sum; __syncthreads();
    for (int o = 64; o > 0; o >>= 1) {
        if (tid < o) red[tid] += red[tid + o];
        __syncthreads();
    }
    float inv = 1.0f / red[0];

    for (int j = tid; j < NT; j += 128)
        s[j] = (j < len) ? expf(s[j] * scale - m) * inv : 0.f;
}

// ------------------------------- loss ---------------------------------------
__global__ void loss_row_kernel(const float* __restrict__ logits,
                                const int* __restrict__ targets,
                                int row0, int ldl) {
    int r = blockIdx.x;
    int tid = threadIdx.x;
    const float* L = logits + (size_t)r * ldl;
    float m = -1e30f, sacc = 0.f;
    for (int j = tid; j < NV; j += 256) {
        float v = L[j];
        if (v > m) { sacc = sacc * expf(m - v) + 1.0f; m = v; }
        else       { sacc += expf(v - m); }
    }
    __shared__ float sm[256], ss[256];
    sm[tid] = m; ss[tid] = sacc; __syncthreads();
    for (int o = 128; o > 0; o >>= 1) {
        if (tid < o) {
            float m2 = sm[tid + o], s2 = ss[tid + o];
            float M  = fmaxf(sm[tid], m2);
            ss[tid]  = ss[tid] * expf(sm[tid] - M) + s2 * expf(m2 - M);
            sm[tid]  = M;
        }
        __syncthreads();
    }
    if (tid == 0) {
        int grow = row0 + r;
        int tgt = targets[grow];
        float nll = 0.f;
        if (tgt != -1) nll = sm[0] + logf(ss[0]) - L[tgt];
        g_nll[grow] = nll;
    }
}

__global__ void loss_reduce_kernel(const int* __restrict__ targets,
                                   float* __restrict__ out) {
    int tid = threadIdx.x;
    __shared__ float ssum[256];
    __shared__ int scnt[256];
    float s = 0.f; int c = 0;
    for (int r = tid; r < NM; r += 256)
        if (targets[r] != -1) { s += g_nll[r]; c++; }
    ssum[tid] = s; scnt[tid] = c; __syncthreads();
    for (int o = 128; o > 0; o >>= 1) {
        if (tid < o) { ssum[tid] += ssum[tid + o]; scnt[tid] += scnt[tid + o]; }
        __syncthreads();
    }
    if (tid == 0) out[0] = ssum[0] / (float)max(scnt[0], 1);
}

// ------------------------------- host ---------------------------------------
static const int MMA_SMEM = 4 * TILE_U * (int)sizeof(unsigned);   // 73728 B

template <int EPI>
static void launch_mma(const float* A, const float* B, float* C,
                       int M, int N, int K, int lda, int ldb, int ldc,
                       int batch = 1, int zdiv = 1,
                       long long sAb = 0, long long sAh = 0,
                       long long sBb = 0, long long sBh = 0,
                       long long sCb = 0, long long sCh = 0) {
    dim3 grid((N + 127) / 128, M / 128, batch);
    mma_gemm<EPI><<<grid, 256, MMA_SMEM>>>(A, B, C, M, N, K, lda, ldb, ldc,
                                           zdiv, sAb, sAh, sBb, sBh, sCb, sCh);
}

extern "C" void kernel_launch(void* const* d_in, const int* in_sizes, int n_in,
                              void* d_out, int out_size) {
    const int*   idx      = (const int*)  d_in[0];
    const int*   targets  = (const int*)  d_in[1];
    const float* wte      = (const float*)d_in[2];
    const float* wpe      = (const float*)d_in[3];
    const float* ln1_w    = (const float*)d_in[4];
    const float* ln1_b    = (const float*)d_in[5];
    const float* attn_w   = (const float*)d_in[6];
    const float* attn_pw  = (const float*)d_in[7];
    const float* ln2_w    = (const float*)d_in[8];
    const float* ln2_b    = (const float*)d_in[9];
    const float* fc_w     = (const float*)d_in[10];
    const float* fc_pw    = (const float*)d_in[11];
    const float* lnf_w    = (const float*)d_in[12];
    const float* lnf_b    = (const float*)d_in[13];
    const float* lm_w     = (const float*)d_in[14];

    cudaFuncSetAttribute(mma_gemm<0>, cudaFuncAttributeMaxDynamicSharedMemorySize, MMA_SMEM);
    cudaFuncSetAttribute(mma_gemm<1>, cudaFuncAttributeMaxDynamicSharedMemorySize, MMA_SMEM);
    cudaFuncSetAttribute(mma_gemm<2>, cudaFuncAttributeMaxDynamicSharedMemorySize, MMA_SMEM);

    float *x, *h, *qkv, *y, *fc, *vt, *att;
    cudaGetSymbolAddress((void**)&x,   g_x);
    cudaGetSymbolAddress((void**)&h,   g_h);
    cudaGetSymbolAddress((void**)&qkv, g_qkv);
    cudaGetSymbolAddress((void**)&y,   g_y);
    cudaGetSymbolAddress((void**)&fc,  g_fc);
    cudaGetSymbolAddress((void**)&vt,  g_vt);
    cudaGetSymbolAddress((void**)&att, g_att);

    embed_kernel<<<NM, 256>>>(idx, wte, wpe);

    const long long sQKVb = (long long)NT * 3 * NE;
    const long long sAttB = (long long)NH * NT * NT;
    const long long sAttH = (long long)NT * NT;

    for (int i = 0; i < NLAYER; i++) {
        const float* aw  = attn_w  + (size_t)i * 3 * NE * NE;
        const float* pw  = attn_pw + (size_t)i * NE * NE;
        const float* fw  = fc_w    + (size_t)i * 4 * NE * NE;
        const float* fpw = fc_pw   + (size_t)i * NE * 4 * NE;

        // ln1
        ln_kernel<<<NM, 256>>>(x, ln1_w + i * NE, ln1_b + i * NE, h);
        // qkv = h @ attn_w^T   (4096 x 3072 x 1024)
        launch_mma<0>(h, aw, qkv, NM, 3 * NE, NE, NE, NE, 3 * NE);
        // S = Q @ K^T, batched over (b,h)
        launch_mma<0>(qkv, qkv + NE, att,
                      NT, NT, HDIM, 3 * NE, 3 * NE, NT,
                      NB * NH, NH,
                      sQKVb, 64, sQKVb, 64, sAttB, sAttH);
        // causal softmax
        softmax_kernel<<<dim3(NT, NB * NH), 128>>>();
        // V^T per (b,h)
        transpose_v_kernel<<<dim3(NT / 32, NB * NH), dim3(32, 8)>>>();
        // Y = P @ V  via  A=P, B=V^T ([64,1024] rows)
        launch_mma<0>(att, vt, y,
                      NT, HDIM, NT, NT, NT, NE,
                      NB * NH, NH,
                      sAttB, sAttH,
                      (long long)NH * HDIM * NT, (long long)HDIM * NT,
                      (long long)NT * NE, 64);
        // x += y @ attn_proj_w^T
        launch_mma<2>(y, pw, x, NM, NE, NE, NE, NE, NE);
        // ln2
        ln_kernel<<<NM, 256>>>(x, ln2_w + i * NE, ln2_b + i * NE, h);
        // fc = gelu(h @ fc_w^T)
        launch_mma<1>(h, fw, fc, NM, 4 * NE, NE, NE, NE, 4 * NE);
        // x += fc @ fc_proj_w^T
        launch_mma<2>(fc, fpw, x, NM, NE, 4 * NE, 4 * NE, 4 * NE, NE);
    }

    // final layernorm
    ln_kernel<<<NM, 256>>>(x, lnf_w, lnf_b, h);

    const size_t P = (size_t)NM * NV;
    float* out = (float*)d_out;

    if ((size_t)out_size >= P) {
        launch_mma<0>(h, lm_w, out, NM, NV, NE, NE, NE, NV);
        loss_row_kernel<<<NM, 256>>>(out, targets, 0, NV);
        if ((size_t)out_size >= P + 1)
            loss_reduce_kernel<<<1, 256>>>(targets, out + P);
    } else {
        const int CHUNK = 1024;
        for (int c = 0; c < NM / CHUNK; c++) {
            launch_mma<0>(h + (size_t)c * CHUNK * NE, lm_w, att,
                          CHUNK, NV, NE, NE, NE, NV);
            loss_row_kernel<<<CHUNK, 256>>>(att, targets, c * CHUNK, NV);
        }
        int li = (out_size >= 1) ? out_size - 1 : 0;
        loss_reduce_kernel<<<1, 256>>>(targets, out + li);
    }
}

// round 3
// speedup vs baseline: 2.9262x; 1.5262x over previous
#include <cuda_runtime.h>
#include <math.h>

// ---------------------------------------------------------------------------
// NanoGPT forward (B=4, T=1024, E=1024, H=16, L=6, V=50257)
// R3: tf32 mma.sync GEMM with cp.async 4-stage pipeline, 2 CTAs/SM.
// ---------------------------------------------------------------------------

#define NB     4
#define NT     1024
#define NE     1024
#define NH     16
#define HDIM   64
#define NLAYER 6
#define NV     50257
#define NM     (NB * NT)
#define LN_EPS 1e-5f

// ------------------------------- scratch -----------------------------------
__device__ float g_x  [NM * NE];
__device__ float g_h  [NM * NE];
__device__ float g_qkv[NM * 3 * NE];
__device__ float g_y  [NM * NE];
__device__ float g_fc [NM * 4 * NE];
__device__ float g_vt [NB * NH * HDIM * NT];
__device__ float g_att[(size_t)NB * NH * NT * NT];
__device__ float g_nll[NM];

// ------------------------------- embed -------------------------------------
__global__ void embed_kernel(const int* __restrict__ idx,
                             const float* __restrict__ wte,
                             const float* __restrict__ wpe) {
    int row = blockIdx.x;
    int t   = row % NT;
    int tok = idx[row];
    const float* s = wte + (size_t)tok * NE;
    const float* p = wpe + (size_t)t * NE;
    float* o = g_x + (size_t)row * NE;
    for (int c = threadIdx.x; c < NE; c += blockDim.x)
        o[c] = s[c] + p[c];
}

// ------------------------------ layernorm -----------------------------------
__global__ void ln_kernel(const float* __restrict__ in,
                          const float* __restrict__ w,
                          const float* __restrict__ b,
                          float* __restrict__ out) {
    int row = blockIdx.x;
    int tid = threadIdx.x;
    const float* x = in + (size_t)row * NE;
    float* o = out + (size_t)row * NE;
    __shared__ float red[256];
    __shared__ float s_mu, s_rstd;

    float s = 0.f;
    for (int c = tid; c < NE; c += 256) s += x[c];
    red[tid] = s; __syncthreads();
    for (int o2 = 128; o2 > 0; o2 >>= 1) {
        if (tid < o2) red[tid] += red[tid + o2];
        __syncthreads();
    }
    if (tid == 0) s_mu = red[0] * (1.0f / NE);
    __syncthreads();
    float mu = s_mu;

    float v = 0.f;
    for (int c = tid; c < NE; c += 256) { float d = x[c] - mu; v += d * d; }
    red[tid] = v; __syncthreads();
    for (int o2 = 128; o2 > 0; o2 >>= 1) {
        if (tid < o2) red[tid] += red[tid + o2];
        __syncthreads();
    }
    if (tid == 0) s_rstd = rsqrtf(red[0] * (1.0f / NE) + LN_EPS);
    __syncthreads();
    float rstd = s_rstd;

    for (int c = tid; c < NE; c += 256)
        o[c] = (x[c] - mu) * rstd * w[c] + b[c];
}

// ------------------------- tf32 tensor-core GEMM -----------------------------
// C[M,N] = A[M,K] * B^T (B stored [N,K]).  EPI: 0 store, 1 gelu, 2 +=.
// Block 128x128, BK=16, 4-stage cp.async pipeline, 256 thr, warp tile 64x32.
// Requires M % 128 == 0, K % 16 == 0.

__device__ __forceinline__ unsigned f2tf(float f) {
    unsigned u;
    asm("cvt.rna.tf32.f32 %0, %1;" : "=r"(u) : "f"(f));
    return u;
}

__device__ __forceinline__ void mma8(float* c, const unsigned* a, const unsigned* b) {
    asm volatile(
        "mma.sync.aligned.m16n8k8.row.col.f32.tf32.tf32.f32 "
        "{%0,%1,%2,%3}, {%4,%5,%6,%7}, {%8,%9}, {%0,%1,%2,%3};"
        : "+f"(c[0]), "+f"(c[1]), "+f"(c[2]), "+f"(c[3])
        : "r"(a[0]), "r"(a[1]), "r"(a[2]), "r"(a[3]),
          "r"(b[0]), "r"(b[1]));
}

__device__ __forceinline__ void cpasync16(float* dst, const float* src, bool full) {
    unsigned d = (unsigned)__cvta_generic_to_shared(dst);
    int sz = full ? 16 : 0;
    asm volatile("cp.async.cg.shared.global [%0], [%1], 16, %2;"
                 :: "r"(d), "l"(src), "r"(sz));
}

__device__ __forceinline__ float gelu_f(float x) {
    return 0.5f * x * (1.0f + erff(x * 0.70710678118654752f));
}

#define BKT    16
#define STAGES 4
#define APAD   20                        // float row stride (bank-conflict free)
#define STG_F  (2 * 128 * APAD)          // floats per stage (A + B)

template <int EPI>
__global__ void __launch_bounds__(256, 2)
mma_gemm(const float* __restrict__ A, const float* __restrict__ B,
         float* __restrict__ C,
         int M, int N, int K, int lda, int ldb, int ldc,
         int zdiv,
         long long sAb, long long sAh,
         long long sBb, long long sBh,
         long long sCb, long long sCh) {
    extern __shared__ float sh[];
    int z = blockIdx.z;
    int zb = z / zdiv, zh = z % zdiv;
    A += zb * sAb + zh * sAh;
    B += zb * sBb + zh * sBh;
    C += zb * sCb + zh * sCh;

    const int bm   = blockIdx.y * 128;
    const int bn   = blockIdx.x * 128;
    const int tid  = threadIdx.x;
    const int lane = tid & 31;
    const int wid  = tid >> 5;
    const int wm   = (wid >> 2) * 64;
    const int wn   = (wid & 3) * 32;
    const int lr   = lane >> 2;
    const int lc   = lane & 3;

    // per-thread load slots: 2 chunks for A, 2 for B (128 rows x 4 chunks)
    const int r0c = (tid + 0)   >> 2, k0c = ((tid + 0)   & 3) << 2;
    const int r1c = (tid + 256) >> 2, k1c = ((tid + 256) & 3) << 2;

    const float* Ar0 = A + (size_t)(bm + r0c) * lda + k0c;
    const float* Ar1 = A + (size_t)(bm + r1c) * lda + k1c;
    const bool bv0 = (bn + r0c) < N;
    const bool bv1 = (bn + r1c) < N;
    const float* Br0 = B + (size_t)min(bn + r0c, N - 1) * ldb + k0c;
    const float* Br1 = B + (size_t)min(bn + r1c, N - 1) * ldb + k1c;

    float acc[4][4][4];
#pragma unroll
    for (int i = 0; i < 4; i++)
#pragma unroll
        for (int j = 0; j < 4; j++)
#pragma unroll
            for (int q = 0; q < 4; q++) acc[i][j][q] = 0.f;

    const int KT = K / BKT;

    // prologue: stage first STAGES-1 k-tiles
#pragma unroll
    for (int s = 0; s < STAGES - 1; s++) {
        float* sA = sh + s * STG_F;
        float* sB = sA + 128 * APAD;
        int k0 = s * BKT;
        cpasync16(sA + r0c * APAD + k0c, Ar0 + k0, true);
        cpasync16(sA + r1c * APAD + k1c, Ar1 + k0, true);
        cpasync16(sB + r0c * APAD + k0c, Br0 + k0, bv0);
        cpasync16(sB + r1c * APAD + k1c, Br1 + k0, bv1);
        asm volatile("cp.async.commit_group;");
    }

    for (int kt = 0; kt < KT; kt++) {
        asm volatile("cp.async.wait_group %0;" :: "n"(STAGES - 2));
        __syncthreads();

        // prefetch k-tile kt+STAGES-1 into the buffer freed last iteration
        int pf = kt + STAGES - 1;
        if (pf < KT) {
            float* sA = sh + (pf % STAGES) * STG_F;
            float* sB = sA + 128 * APAD;
            int k0 = pf * BKT;
            cpasync16(sA + r0c * APAD + k0c, Ar0 + k0, true);
            cpasync16(sA + r1c * APAD + k1c, Ar1 + k0, true);
            cpasync16(sB + r0c * APAD + k0c, Br0 + k0, bv0);
            cpasync16(sB + r1c * APAD + k1c, Br1 + k0, bv1);
        }
        asm volatile("cp.async.commit_group;");

        const float* As = sh + (kt % STAGES) * STG_F;
        const float* Bs = As + 128 * APAD;
#pragma unroll
        for (int ks = 0; ks < 2; ks++) {
            unsigned afr[4][4], bfr[4][2];
#pragma unroll
            for (int i = 0; i < 4; i++) {
                const float* p = &As[(wm + i * 16 + lr) * APAD + ks * 8 + lc];
                afr[i][0] = f2tf(p[0]);
                afr[i][1] = f2tf(p[8 * APAD]);
                afr[i][2] = f2tf(p[4]);
                afr[i][3] = f2tf(p[8 * APAD + 4]);
            }
#pragma unroll
            for (int j = 0; j < 4; j++) {
                const float* p = &Bs[(wn + j * 8 + lr) * APAD + ks * 8 + lc];
                bfr[j][0] = f2tf(p[0]);
                bfr[j][1] = f2tf(p[4]);
            }
#pragma unroll
            for (int i = 0; i < 4; i++)
#pragma unroll
                for (int j = 0; j < 4; j++)
                    mma8(acc[i][j], afr[i], bfr[j]);
        }
        __syncthreads();
    }

    // ---- epilogue ----
#pragma unroll
    for (int i = 0; i < 4; i++) {
        int r0 = bm + wm + i * 16 + lr;
        float* C0 = C + (size_t)r0 * ldc;
        float* C1 = C0 + (size_t)8 * ldc;
#pragma unroll
        for (int j = 0; j < 4; j++) {
            int c0 = bn + wn + j * 8 + (lc << 1);
            const float* a4 = acc[i][j];
#pragma unroll
            for (int q = 0; q < 2; q++) {
                int col = c0 + q;
                if (col < N) {
                    if (EPI == 0) {
                        C0[col] = a4[q];
                        C1[col] = a4[q + 2];
                    } else if (EPI == 1) {
                        C0[col] = gelu_f(a4[q]);
                        C1[col] = gelu_f(a4[q + 2]);
                    } else {
                        C0[col] += a4[q];
                        C1[col] += a4[q + 2];
                    }
                }
            }
        }
    }
}

// --------------------------- V transpose ------------------------------------
__global__ void transpose_v_kernel() {
    __shared__ float tile[32][33];
    int bh = blockIdx.y;
    int b = bh >> 4, h = bh & 15;
    int t0 = blockIdx.x * 32;
    int tx = threadIdx.x, ty = threadIdx.y;
    const float* src = g_qkv + (size_t)b * NT * (3 * NE) + 2 * NE + h * 64;
    float* dst = g_vt + (size_t)bh * HDIM * NT;
    for (int d0 = 0; d0 < HDIM; d0 += 32) {
#pragma unroll
        for (int i = 0; i < 32; i += 8)
            tile[ty + i][tx] = src[(size_t)(t0 + ty + i) * (3 * NE) + d0 + tx];
        __syncthreads();
#pragma unroll
        for (int i = 0; i < 32; i += 8)
            dst[(size_t)(d0 + ty + i) * NT + t0 + tx] = tile[tx][ty + i];
        __syncthreads();
    }
}

// ------------------------------ softmax -------------------------------------
__global__ void softmax_kernel() {
    int q  = blockIdx.x;
    int bh = blockIdx.y;
    float* s = g_att + (size_t)bh * NT * NT + (size_t)q * NT;
    int len = q + 1;
    const float scale = 0.125f;
    int tid = threadIdx.x;
    __shared__ float red[128];

    float m = -1e30f;
    for (int j = tid; j < len; j += 128) m = fmaxf(m, s[j] * scale);
    red[tid] = m; __syncthreads();
    for (int o = 64; o > 0; o >>= 1) {
        if (tid < o) red[tid] = fmaxf(red[tid], red[tid + o]);
        __syncthreads();
    }
    m = red[0]; __syncthreads();

    float sum = 0.f;
    for (int j = tid; j < len; j += 128) sum += expf(s[j] * scale - m);
    red[tid] = sum; __syncthreads();
    for (int o = 64; o > 0; o >>= 1) {
        if (tid < o) red[tid] += red[tid + o];
        __syncthreads();
    }
    float inv = 1.0f / red[0];

    for (int j = tid; j < NT; j += 128)
        s[j] = (j < len) ? expf(s[j] * scale - m) * inv : 0.f;
}

// ------------------------------- loss ---------------------------------------
__global__ void loss_row_kernel(const float* __restrict__ logits,
                                const int* __restrict__ targets,
                                int row0, int ldl) {
    int r = blockIdx.x;
    int tid = threadIdx.x;
    const float* L = logits + (size_t)r * ldl;
    float m = -1e30f, sacc = 0.f;
    for (int j = tid; j < NV; j += 256) {
        float v = L[j];
        if (v > m) { sacc = sacc * expf(m - v) + 1.0f; m = v; }
        else       { sacc += expf(v - m); }
    }
    __shared__ float sm[256], ss[256];
    sm[tid] = m; ss[tid] = sacc; __syncthreads();
    for (int o = 128; o > 0; o >>= 1) {
        if (tid < o) {
            float m2 = sm[tid + o], s2 = ss[tid + o];
            float M  = fmaxf(sm[tid], m2);
            ss[tid]  = ss[tid] * expf(sm[tid] - M) + s2 * expf(m2 - M);
            sm[tid]  = M;
        }
        __syncthreads();
    }
    if (tid == 0) {
        int grow = row0 + r;
        int tgt = targets[grow];
        float nll = 0.f;
        if (tgt != -1) nll = sm[0] + logf(ss[0]) - L[tgt];
        g_nll[grow] = nll;
    }
}

__global__ void loss_reduce_kernel(const int* __restrict__ targets,
                                   float* __restrict__ out) {
    int tid = threadIdx.x;
    __shared__ float ssum[256];
    __shared__ int scnt[256];
    float s = 0.f; int c = 0;
    for (int r = tid; r < NM; r += 256)
        if (targets[r] != -1) { s += g_nll[r]; c++; }
    ssum[tid] = s; scnt[tid] = c; __syncthreads();
    for (int o = 128; o > 0; o >>= 1) {
        if (tid < o) { ssum[tid] += ssum[tid + o]; scnt[tid] += scnt[tid + o]; }
        __syncthreads();
    }
    if (tid == 0) out[0] = ssum[0] / (float)max(scnt[0], 1);
}

// ------------------------------- host ---------------------------------------
static const int MMA_SMEM = STAGES * STG_F * (int)sizeof(float);   // 81920 B

template <int EPI>
static void launch_mma(const float* A, const float* B, float* C,
                       int M, int N, int K, int lda, int ldb, int ldc,
                       int batch = 1, int zdiv = 1,
                       long long sAb = 0, long long sAh = 0,
                       long long sBb = 0, long long sBh = 0,
                       long long sCb = 0, long long sCh = 0) {
    dim3 grid((N + 127) / 128, M / 128, batch);
    mma_gemm<EPI><<<grid, 256, MMA_SMEM>>>(A, B, C, M, N, K, lda, ldb, ldc,
                                           zdiv, sAb, sAh, sBb, sBh, sCb, sCh);
}

extern "C" void kernel_launch(void* const* d_in, const int* in_sizes, int n_in,
                              void* d_out, int out_size) {
    const int*   idx      = (const int*)  d_in[0];
    const int*   targets  = (const int*)  d_in[1];
    const float* wte      = (const float*)d_in[2];
    const float* wpe      = (const float*)d_in[3];
    const float* ln1_w    = (const float*)d_in[4];
    const float* ln1_b    = (const float*)d_in[5];
    const float* attn_w   = (const float*)d_in[6];
    const float* attn_pw  = (const float*)d_in[7];
    const float* ln2_w    = (const float*)d_in[8];
    const float* ln2_b    = (const float*)d_in[9];
    const float* fc_w     = (const float*)d_in[10];
    const float* fc_pw    = (const float*)d_in[11];
    const float* lnf_w    = (const float*)d_in[12];
    const float* lnf_b    = (const float*)d_in[13];
    const float* lm_w     = (const float*)d_in[14];

    cudaFuncSetAttribute(mma_gemm<0>, cudaFuncAttributeMaxDynamicSharedMemorySize, MMA_SMEM);
    cudaFuncSetAttribute(mma_gemm<1>, cudaFuncAttributeMaxDynamicSharedMemorySize, MMA_SMEM);
    cudaFuncSetAttribute(mma_gemm<2>, cudaFuncAttributeMaxDynamicSharedMemorySize, MMA_SMEM);

    float *x, *h, *qkv, *y, *fc, *vt, *att;
    cudaGetSymbolAddress((void**)&x,   g_x);
    cudaGetSymbolAddress((void**)&h,   g_h);
    cudaGetSymbolAddress((void**)&qkv, g_qkv);
    cudaGetSymbolAddress((void**)&y,   g_y);
    cudaGetSymbolAddress((void**)&fc,  g_fc);
    cudaGetSymbolAddress((void**)&vt,  g_vt);
    cudaGetSymbolAddress((void**)&att, g_att);

    embed_kernel<<<NM, 256>>>(idx, wte, wpe);

    const long long sQKVb = (long long)NT * 3 * NE;
    const long long sAttB = (long long)NH * NT * NT;
    const long long sAttH = (long long)NT * NT;

    for (int i = 0; i < NLAYER; i++) {
        const float* aw  = attn_w  + (size_t)i * 3 * NE * NE;
        const float* pw  = attn_pw + (size_t)i * NE * NE;
        const float* fw  = fc_w    + (size_t)i * 4 * NE * NE;
        const float* fpw = fc_pw   + (size_t)i * NE * 4 * NE;

        ln_kernel<<<NM, 256>>>(x, ln1_w + i * NE, ln1_b + i * NE, h);
        launch_mma<0>(h, aw, qkv, NM, 3 * NE, NE, NE, NE, 3 * NE);
        launch_mma<0>(qkv, qkv + NE, att,
                      NT, NT, HDIM, 3 * NE, 3 * NE, NT,
                      NB * NH, NH,
                      sQKVb, 64, sQKVb, 64, sAttB, sAttH);
        softmax_kernel<<<dim3(NT, NB * NH), 128>>>();
        transpose_v_kernel<<<dim3(NT / 32, NB * NH), dim3(32, 8)>>>();
        launch_mma<0>(att, vt, y,
                      NT, HDIM, NT, NT, NT, NE,
                      NB * NH, NH,
                      sAttB, sAttH,
                      (long long)NH * HDIM * NT, (long long)HDIM * NT,
                      (long long)NT * NE, 64);
        launch_mma<2>(y, pw, x, NM, NE, NE, NE, NE, NE);
        ln_kernel<<<NM, 256>>>(x, ln2_w + i * NE, ln2_b + i * NE, h);
        launch_mma<1>(h, fw, fc, NM, 4 * NE, NE, NE, NE, 4 * NE);
        launch_mma<2>(fc, fpw, x, NM, NE, 4 * NE, 4 * NE, 4 * NE, NE);
    }

    ln_kernel<<<NM, 256>>>(x, lnf_w, lnf_b, h);

    const size_t P = (size_t)NM * NV;
    float* out = (float*)d_out;

    if ((size_t)out_size >= P) {
        launch_mma<0>(h, lm_w, out, NM, NV, NE, NE, NE, NV);
        loss_row_kernel<<<NM, 256>>>(out, targets, 0, NV);
        if ((size_t)out_size >= P + 1)
            loss_reduce_kernel<<<1, 256>>>(targets, out + P);
    } else {
        const int CHUNK = 1024;
        for (int c = 0; c < NM / CHUNK; c++) {
            launch_mma<0>(h + (size_t)c * CHUNK * NE, lm_w, att,
                          CHUNK, NV, NE, NE, NE, NV);
            loss_row_kernel<<<CHUNK, 256>>>(att, targets, c * CHUNK, NV);
        }
        int li = (out_size >= 1) ? out_size - 1 : 0;
        loss_reduce_kernel<<<1, 256>>>(targets, out + li);
    }
}

// round 4
// speedup vs baseline: 3.3530x; 1.1459x over previous
#include <cuda_runtime.h>
#include <math.h>

// ---------------------------------------------------------------------------
// NanoGPT forward (B=4, T=1024, E=1024, H=16, L=6, V=50257)
// R4: fused flash attention (tf32 mma), dense GEMMs from R3 (cp.async tf32).
// ---------------------------------------------------------------------------

#define NB     4
#define NT     1024
#define NE     1024
#define NH     16
#define HDIM   64
#define NLAYER 6
#define NV     50257
#define NM     (NB * NT)
#define LN_EPS 1e-5f

// ------------------------------- scratch -----------------------------------
__device__ float g_x  [NM * NE];
__device__ float g_h  [NM * NE];
__device__ float g_qkv[NM * 3 * NE];
__device__ float g_y  [NM * NE];
__device__ float g_fc [NM * 4 * NE];
__device__ float g_att[(size_t)NM * 51200];   // logits chunk scratch (fallback path)
__device__ float g_nll[NM];

// ------------------------------- embed -------------------------------------
__global__ void embed_kernel(const int* __restrict__ idx,
                             const float* __restrict__ wte,
                             const float* __restrict__ wpe) {
    int row = blockIdx.x;
    int t   = row % NT;
    int tok = idx[row];
    const float* s = wte + (size_t)tok * NE;
    const float* p = wpe + (size_t)t * NE;
    float* o = g_x + (size_t)row * NE;
    for (int c = threadIdx.x; c < NE; c += blockDim.x)
        o[c] = s[c] + p[c];
}

// ------------------------------ layernorm -----------------------------------
__global__ void ln_kernel(const float* __restrict__ in,
                          const float* __restrict__ w,
                          const float* __restrict__ b,
                          float* __restrict__ out) {
    int row = blockIdx.x;
    int tid = threadIdx.x;
    const float* x = in + (size_t)row * NE;
    float* o = out + (size_t)row * NE;
    __shared__ float red[256];
    __shared__ float s_mu, s_rstd;

    float s = 0.f;
    for (int c = tid; c < NE; c += 256) s += x[c];
    red[tid] = s; __syncthreads();
    for (int o2 = 128; o2 > 0; o2 >>= 1) {
        if (tid < o2) red[tid] += red[tid + o2];
        __syncthreads();
    }
    if (tid == 0) s_mu = red[0] * (1.0f / NE);
    __syncthreads();
    float mu = s_mu;

    float v = 0.f;
    for (int c = tid; c < NE; c += 256) { float d = x[c] - mu; v += d * d; }
    red[tid] = v; __syncthreads();
    for (int o2 = 128; o2 > 0; o2 >>= 1) {
        if (tid < o2) red[tid] += red[tid + o2];
        __syncthreads();
    }
    if (tid == 0) s_rstd = rsqrtf(red[0] * (1.0f / NE) + LN_EPS);
    __syncthreads();
    float rstd = s_rstd;

    for (int c = tid; c < NE; c += 256)
        o[c] = (x[c] - mu) * rstd * w[c] + b[c];
}

// ----------------------------- mma helpers ----------------------------------
__device__ __forceinline__ unsigned f2tf(float f) {
    unsigned u;
    asm("cvt.rna.tf32.f32 %0, %1;" : "=r"(u) : "f"(f));
    return u;
}

__device__ __forceinline__ void mma8(float* c, const unsigned* a, const unsigned* b) {
    asm volatile(
        "mma.sync.aligned.m16n8k8.row.col.f32.tf32.tf32.f32 "
        "{%0,%1,%2,%3}, {%4,%5,%6,%7}, {%8,%9}, {%0,%1,%2,%3};"
        : "+f"(c[0]), "+f"(c[1]), "+f"(c[2]), "+f"(c[3])
        : "r"(a[0]), "r"(a[1]), "r"(a[2]), "r"(a[3]),
          "r"(b[0]), "r"(b[1]));
}

__device__ __forceinline__ void cpasync16(float* dst, const float* src, bool full) {
    unsigned d = (unsigned)__cvta_generic_to_shared(dst);
    int sz = full ? 16 : 0;
    asm volatile("cp.async.cg.shared.global [%0], [%1], 16, %2;"
                 :: "r"(d), "l"(src), "r"(sz));
}

__device__ __forceinline__ float gelu_f(float x) {
    return 0.5f * x * (1.0f + erff(x * 0.70710678118654752f));
}

// ------------------------- tf32 tensor-core GEMM -----------------------------
#define BKT    16
#define STAGES 4
#define APAD   20
#define STG_F  (2 * 128 * APAD)

template <int EPI>
__global__ void __launch_bounds__(256, 2)
mma_gemm(const float* __restrict__ A, const float* __restrict__ B,
         float* __restrict__ C,
         int M, int N, int K, int lda, int ldb, int ldc) {
    extern __shared__ float sh[];
    const int bm   = blockIdx.y * 128;
    const int bn   = blockIdx.x * 128;
    const int tid  = threadIdx.x;
    const int lane = tid & 31;
    const int wid  = tid >> 5;
    const int wm   = (wid >> 2) * 64;
    const int wn   = (wid & 3) * 32;
    const int lr   = lane >> 2;
    const int lc   = lane & 3;

    const int r0c = (tid + 0)   >> 2, k0c = ((tid + 0)   & 3) << 2;
    const int r1c = (tid + 256) >> 2, k1c = ((tid + 256) & 3) << 2;

    const float* Ar0 = A + (size_t)(bm + r0c) * lda + k0c;
    const float* Ar1 = A + (size_t)(bm + r1c) * lda + k1c;
    const bool bv0 = (bn + r0c) < N;
    const bool bv1 = (bn + r1c) < N;
    const float* Br0 = B + (size_t)min(bn + r0c, N - 1) * ldb + k0c;
    const float* Br1 = B + (size_t)min(bn + r1c, N - 1) * ldb + k1c;

    float acc[4][4][4];
#pragma unroll
    for (int i = 0; i < 4; i++)
#pragma unroll
        for (int j = 0; j < 4; j++)
#pragma unroll
            for (int q = 0; q < 4; q++) acc[i][j][q] = 0.f;

    const int KT = K / BKT;

#pragma unroll
    for (int s = 0; s < STAGES - 1; s++) {
        float* sA = sh + s * STG_F;
        float* sB = sA + 128 * APAD;
        int k0 = s * BKT;
        cpasync16(sA + r0c * APAD + k0c, Ar0 + k0, true);
        cpasync16(sA + r1c * APAD + k1c, Ar1 + k0, true);
        cpasync16(sB + r0c * APAD + k0c, Br0 + k0, bv0);
        cpasync16(sB + r1c * APAD + k1c, Br1 + k0, bv1);
        asm volatile("cp.async.commit_group;");
    }

    for (int kt = 0; kt < KT; kt++) {
        asm volatile("cp.async.wait_group %0;" :: "n"(STAGES - 2));
        __syncthreads();

        int pf = kt + STAGES - 1;
        if (pf < KT) {
            float* sA = sh + (pf % STAGES) * STG_F;
            float* sB = sA + 128 * APAD;
            int k0 = pf * BKT;
            cpasync16(sA + r0c * APAD + k0c, Ar0 + k0, true);
            cpasync16(sA + r1c * APAD + k1c, Ar1 + k0, true);
            cpasync16(sB + r0c * APAD + k0c, Br0 + k0, bv0);
            cpasync16(sB + r1c * APAD + k1c, Br1 + k0, bv1);
        }
        asm volatile("cp.async.commit_group;");

        const float* As = sh + (kt % STAGES) * STG_F;
        const float* Bs = As + 128 * APAD;
#pragma unroll
        for (int ks = 0; ks < 2; ks++) {
            unsigned afr[4][4], bfr[4][2];
#pragma unroll
            for (int i = 0; i < 4; i++) {
                const float* p = &As[(wm + i * 16 + lr) * APAD + ks * 8 + lc];
                afr[i][0] = f2tf(p[0]);
                afr[i][1] = f2tf(p[8 * APAD]);
                afr[i][2] = f2tf(p[4]);
                afr[i][3] = f2tf(p[8 * APAD + 4]);
            }
#pragma unroll
            for (int j = 0; j < 4; j++) {
                const float* p = &Bs[(wn + j * 8 + lr) * APAD + ks * 8 + lc];
                bfr[j][0] = f2tf(p[0]);
                bfr[j][1] = f2tf(p[4]);
            }
#pragma unroll
            for (int i = 0; i < 4; i++)
#pragma unroll
                for (int j = 0; j < 4; j++)
                    mma8(acc[i][j], afr[i], bfr[j]);
        }
        __syncthreads();
    }

#pragma unroll
    for (int i = 0; i < 4; i++) {
        int r0 = bm + wm + i * 16 + lr;
        float* C0 = C + (size_t)r0 * ldc;
        float* C1 = C0 + (size_t)8 * ldc;
#pragma unroll
        for (int j = 0; j < 4; j++) {
            int c0 = bn + wn + j * 8 + (lc << 1);
            const float* a4 = acc[i][j];
#pragma unroll
            for (int q = 0; q < 2; q++) {
                int col = c0 + q;
                if (col < N) {
                    if (EPI == 0) {
                        C0[col] = a4[q];
                        C1[col] = a4[q + 2];
                    } else if (EPI == 1) {
                        C0[col] = gelu_f(a4[q]);
                        C1[col] = gelu_f(a4[q + 2]);
                    } else {
                        C0[col] += a4[q];
                        C1[col] += a4[q + 2];
                    }
                }
            }
        }
    }
}

// --------------------------- flash attention ---------------------------------
// CTA: 128 q-rows of one (b,h). 8 warps x 16 q-rows. kv-tiles of 64.
// smem: sK[64x68] | sV[64x68] | sP[128x68] (Q staged in sP first).
#define FPAD 68
#define FA_SMEM ((64 * FPAD + 64 * FPAD + 128 * FPAD) * (int)sizeof(float))

__global__ void __launch_bounds__(256, 2)
flash_attn_kernel() {
    extern __shared__ float fsh[];
    float* sK = fsh;
    float* sV = sK + 64 * FPAD;
    float* sP = sV + 64 * FPAD;

    const int qt  = blockIdx.x;          // 0..7
    const int bh  = blockIdx.y;          // 0..63
    const int b   = bh >> 4, h = bh & 15;
    const int tid = threadIdx.x;
    const int w   = tid >> 5;
    const int lane = tid & 31;
    const int lr  = lane >> 2;
    const int lc  = lane & 3;
    const int wrow = w * 16 + lr;        // q-row (lo) within tile

    const float* base = g_qkv + (size_t)b * NT * 3 * NE + h * 64;

    // ---- stage Q tile (128 x 64) into sP, cache fragments in regs ----
    {
        const float* Qg = base + (size_t)(qt * 128) * 3 * NE;
#pragma unroll
        for (int i = 0; i < 8; i++) {
            int idx = tid + i * 256;
            int row = idx >> 4, c4 = (idx & 15) << 2;
            *(float4*)&sP[row * FPAD + c4] =
                *(const float4*)(Qg + (size_t)row * 3 * NE + c4);
        }
    }
    __syncthreads();

    unsigned qf[8][4];
#pragma unroll
    for (int ks = 0; ks < 8; ks++) {
        qf[ks][0] = f2tf(sP[wrow * FPAD + ks * 8 + lc]);
        qf[ks][1] = f2tf(sP[(wrow + 8) * FPAD + ks * 8 + lc]);
        qf[ks][2] = f2tf(sP[wrow * FPAD + ks * 8 + lc + 4]);
        qf[ks][3] = f2tf(sP[(wrow + 8) * FPAD + ks * 8 + lc + 4]);
    }
    __syncthreads();

    float oacc[8][4];
#pragma unroll
    for (int j = 0; j < 8; j++)
#pragma unroll
        for (int q = 0; q < 4; q++) oacc[j][q] = 0.f;
    float m0 = -1e30f, m1 = -1e30f, l0 = 0.f, l1 = 0.f;

    const int row0 = qt * 128 + wrow;
    const int row1 = row0 + 8;
    const int ntiles = 2 * qt + 2;

    for (int j = 0; j < ntiles; j++) {
        // ---- load K, V tiles (64 x 64) ----
        const float* Kg = base + (size_t)(j * 64) * 3 * NE + NE;
        const float* Vg = base + (size_t)(j * 64) * 3 * NE + 2 * NE;
#pragma unroll
        for (int i = 0; i < 4; i++) {
            int idx = tid + i * 256;
            int row = idx >> 4, c4 = (idx & 15) << 2;
            cpasync16(sK + row * FPAD + c4, Kg + (size_t)row * 3 * NE + c4, true);
            cpasync16(sV + row * FPAD + c4, Vg + (size_t)row * 3 * NE + c4, true);
        }
        asm volatile("cp.async.commit_group;");
        asm volatile("cp.async.wait_group 0;");
        __syncthreads();

        // ---- S = Q K^T  (warp tile 16 x 64) ----
        float sacc[8][4];
#pragma unroll
        for (int jn = 0; jn < 8; jn++)
#pragma unroll
            for (int q = 0; q < 4; q++) sacc[jn][q] = 0.f;
#pragma unroll
        for (int jn = 0; jn < 8; jn++) {
#pragma unroll
            for (int ks = 0; ks < 8; ks++) {
                unsigned bf[2];
                const float* p = &sK[(jn * 8 + lr) * FPAD + ks * 8 + lc];
                bf[0] = f2tf(p[0]);
                bf[1] = f2tf(p[4]);
                mma8(sacc[jn], qf[ks], bf);
            }
        }

        // ---- mask + scale, tile row-max ----
        const float sc = 0.125f;
        float tm0 = -1e30f, tm1 = -1e30f;
#pragma unroll
        for (int jn = 0; jn < 8; jn++) {
            int col = j * 64 + jn * 8 + (lc << 1);
            sacc[jn][0] = (col     <= row0) ? sacc[jn][0] * sc : -1e30f;
            sacc[jn][1] = (col + 1 <= row0) ? sacc[jn][1] * sc : -1e30f;
            sacc[jn][2] = (col     <= row1) ? sacc[jn][2] * sc : -1e30f;
            sacc[jn][3] = (col + 1 <= row1) ? sacc[jn][3] * sc : -1e30f;
            tm0 = fmaxf(tm0, fmaxf(sacc[jn][0], sacc[jn][1]));
            tm1 = fmaxf(tm1, fmaxf(sacc[jn][2], sacc[jn][3]));
        }
        tm0 = fmaxf(tm0, __shfl_xor_sync(0xffffffffu, tm0, 1));
        tm0 = fmaxf(tm0, __shfl_xor_sync(0xffffffffu, tm0, 2));
        tm1 = fmaxf(tm1, __shfl_xor_sync(0xffffffffu, tm1, 1));
        tm1 = fmaxf(tm1, __shfl_xor_sync(0xffffffffu, tm1, 2));

        float mn0 = fmaxf(m0, tm0), mn1 = fmaxf(m1, tm1);
        float a0 = expf(m0 - mn0),  a1 = expf(m1 - mn1);
        m0 = mn0; m1 = mn1;

        // ---- exponentiate, store P (tf32 bits), row sums ----
        float rs0 = 0.f, rs1 = 0.f;
#pragma unroll
        for (int jn = 0; jn < 8; jn++) {
            float p0 = expf(sacc[jn][0] - m0);
            float p1 = expf(sacc[jn][1] - m0);
            float p2 = expf(sacc[jn][2] - m1);
            float p3 = expf(sacc[jn][3] - m1);
            rs0 += p0 + p1;
            rs1 += p2 + p3;
            int cc = jn * 8 + (lc << 1);
            sP[wrow * FPAD + cc]           = __uint_as_float(f2tf(p0));
            sP[wrow * FPAD + cc + 1]       = __uint_as_float(f2tf(p1));
            sP[(wrow + 8) * FPAD + cc]     = __uint_as_float(f2tf(p2));
            sP[(wrow + 8) * FPAD + cc + 1] = __uint_as_float(f2tf(p3));
        }
        rs0 += __shfl_xor_sync(0xffffffffu, rs0, 1);
        rs0 += __shfl_xor_sync(0xffffffffu, rs0, 2);
        rs1 += __shfl_xor_sync(0xffffffffu, rs1, 1);
        rs1 += __shfl_xor_sync(0xffffffffu, rs1, 2);
        l0 = l0 * a0 + rs0;
        l1 = l1 * a1 + rs1;
#pragma unroll
        for (int jo = 0; jo < 8; jo++) {
            oacc[jo][0] *= a0; oacc[jo][1] *= a0;
            oacc[jo][2] *= a1; oacc[jo][3] *= a1;
        }
        __syncwarp();

        // ---- O += P V ----
#pragma unroll
        for (int jo = 0; jo < 8; jo++) {
#pragma unroll
            for (int ks = 0; ks < 8; ks++) {
                unsigned af[4], bf[2];
                af[0] = __float_as_uint(sP[wrow * FPAD + ks * 8 + lc]);
                af[1] = __float_as_uint(sP[(wrow + 8) * FPAD + ks * 8 + lc]);
                af[2] = __float_as_uint(sP[wrow * FPAD + ks * 8 + lc + 4]);
                af[3] = __float_as_uint(sP[(wrow + 8) * FPAD + ks * 8 + lc + 4]);
                bf[0] = f2tf(sV[(ks * 8 + lc) * FPAD + jo * 8 + lr]);
                bf[1] = f2tf(sV[(ks * 8 + lc + 4) * FPAD + jo * 8 + lr]);
                mma8(oacc[jo], af, bf);
            }
        }
        __syncthreads();   // protect sK/sV/sP before next tile
    }

    // ---- finalize: O /= l, write to g_y ----
    float inv0 = 1.0f / l0, inv1 = 1.0f / l1;
    float* y0 = g_y + ((size_t)b * NT + row0) * NE + h * 64;
    float* y1 = y0 + (size_t)8 * NE;
#pragma unroll
    for (int jo = 0; jo < 8; jo++) {
        int col = jo * 8 + (lc << 1);
        y0[col]     = oacc[jo][0] * inv0;
        y0[col + 1] = oacc[jo][1] * inv0;
        y1[col]     = oacc[jo][2] * inv1;
        y1[col + 1] = oacc[jo][3] * inv1;
    }
}

// ------------------------------- loss ---------------------------------------
__global__ void loss_row_kernel(const float* __restrict__ logits,
                                const int* __restrict__ targets,
                                int row0, int ldl) {
    int r = blockIdx.x;
    int tid = threadIdx.x;
    const float* L = logits + (size_t)r * ldl;
    float m = -1e30f, sacc = 0.f;
    for (int j = tid; j < NV; j += 256) {
        float v = L[j];
        if (v > m) { sacc = sacc * expf(m - v) + 1.0f; m = v; }
        else       { sacc += expf(v - m); }
    }
    __shared__ float sm[256], ss[256];
    sm[tid] = m; ss[tid] = sacc; __syncthreads();
    for (int o = 128; o > 0; o >>= 1) {
        if (tid < o) {
            float m2 = sm[tid + o], s2 = ss[tid + o];
            float M  = fmaxf(sm[tid], m2);
            ss[tid]  = ss[tid] * expf(sm[tid] - M) + s2 * expf(m2 - M);
            sm[tid]  = M;
        }
        __syncthreads();
    }
    if (tid == 0) {
        int grow = row0 + r;
        int tgt = targets[grow];
        float nll = 0.f;
        if (tgt != -1) nll = sm[0] + logf(ss[0]) - L[tgt];
        g_nll[grow] = nll;
    }
}

__global__ void loss_reduce_kernel(const int* __restrict__ targets,
                                   float* __restrict__ out) {
    int tid = threadIdx.x;
    __shared__ float ssum[256];
    __shared__ int scnt[256];
    float s = 0.f; int c = 0;
    for (int r = tid; r < NM; r += 256)
        if (targets[r] != -1) { s += g_nll[r]; c++; }
    ssum[tid] = s; scnt[tid] = c; __syncthreads();
    for (int o = 128; o > 0; o >>= 1) {
        if (tid < o) { ssum[tid] += ssum[tid + o]; scnt[tid] += scnt[tid + o]; }
        __syncthreads();
    }
    if (tid == 0) out[0] = ssum[0] / (float)max(scnt[0], 1);
}

// ------------------------------- host ---------------------------------------
static const int MMA_SMEM = STAGES * STG_F * (int)sizeof(float);   // 81920 B

template <int EPI>
static void launch_mma(const float* A, const float* B, float* C,
                       int M, int N, int K, int lda, int ldb, int ldc) {
    dim3 grid((N + 127) / 128, M / 128);
    mma_gemm<EPI><<<grid, 256, MMA_SMEM>>>(A, B, C, M, N, K, lda, ldb, ldc);
}

extern "C" void kernel_launch(void* const* d_in, const int* in_sizes, int n_in,
                              void* d_out, int out_size) {
    const int*   idx      = (const int*)  d_in[0];
    const int*   targets  = (const int*)  d_in[1];
    const float* wte      = (const float*)d_in[2];
    const float* wpe      = (const float*)d_in[3];
    const float* ln1_w    = (const float*)d_in[4];
    const float* ln1_b    = (const float*)d_in[5];
    const float* attn_w   = (const float*)d_in[6];
    const float* attn_pw  = (const float*)d_in[7];
    const float* ln2_w    = (const float*)d_in[8];
    const float* ln2_b    = (const float*)d_in[9];
    const float* fc_w     = (const float*)d_in[10];
    const float* fc_pw    = (const float*)d_in[11];
    const float* lnf_w    = (const float*)d_in[12];
    const float* lnf_b    = (const float*)d_in[13];
    const float* lm_w     = (const float*)d_in[14];

    cudaFuncSetAttribute(mma_gemm<0>, cudaFuncAttributeMaxDynamicSharedMemorySize, MMA_SMEM);
    cudaFuncSetAttribute(mma_gemm<1>, cudaFuncAttributeMaxDynamicSharedMemorySize, MMA_SMEM);
    cudaFuncSetAttribute(mma_gemm<2>, cudaFuncAttributeMaxDynamicSharedMemorySize, MMA_SMEM);
    cudaFuncSetAttribute(flash_attn_kernel, cudaFuncAttributeMaxDynamicSharedMemorySize, FA_SMEM);

    float *x, *h, *qkv, *y, *fc, *att;
    cudaGetSymbolAddress((void**)&x,   g_x);
    cudaGetSymbolAddress((void**)&h,   g_h);
    cudaGetSymbolAddress((void**)&qkv, g_qkv);
    cudaGetSymbolAddress((void**)&y,   g_y);
    cudaGetSymbolAddress((void**)&fc,  g_fc);
    cudaGetSymbolAddress((void**)&att, g_att);

    embed_kernel<<<NM, 256>>>(idx, wte, wpe);

    for (int i = 0; i < NLAYER; i++) {
        const float* aw  = attn_w  + (size_t)i * 3 * NE * NE;
        const float* pw  = attn_pw + (size_t)i * NE * NE;
        const float* fw  = fc_w    + (size_t)i * 4 * NE * NE;
        const float* fpw = fc_pw   + (size_t)i * NE * 4 * NE;

        ln_kernel<<<NM, 256>>>(x, ln1_w + i * NE, ln1_b + i * NE, h);
        launch_mma<0>(h, aw, qkv, NM, 3 * NE, NE, NE, NE, 3 * NE);
        flash_attn_kernel<<<dim3(NT / 128, NB * NH), 256, FA_SMEM>>>();
        launch_mma<2>(y, pw, x, NM, NE, NE, NE, NE, NE);
        ln_kernel<<<NM, 256>>>(x, ln2_w + i * NE, ln2_b + i * NE, h);
        launch_mma<1>(h, fw, fc, NM, 4 * NE, NE, NE, NE, 4 * NE);
        launch_mma<2>(fc, fpw, x, NM, NE, 4 * NE, 4 * NE, 4 * NE, NE);
    }

    ln_kernel<<<NM, 256>>>(x, lnf_w, lnf_b, h);

    const size_t P = (size_t)NM * NV;
    float* out = (float*)d_out;

    if ((size_t)out_size >= P) {
        launch_mma<0>(h, lm_w, out, NM, NV, NE, NE, NE, NV);
        loss_row_kernel<<<NM, 256>>>(out, targets, 0, NV);
        if ((size_t)out_size >= P + 1)
            loss_reduce_kernel<<<1, 256>>>(targets, out + P);
    } else {
        const int CHUNK = 1024;
        for (int c = 0; c < NM / CHUNK; c++) {
            launch_mma<0>(h + (size_t)c * CHUNK * NE, lm_w, att,
                          CHUNK, NV, NE, NE, NE, NV);
            loss_row_kernel<<<CHUNK, 256>>>(att, targets, c * CHUNK, NV);
        }
        int li = (out_size >= 1) ? out_size - 1 : 0;
        loss_reduce_kernel<<<1, 256>>>(targets, out + li);
    }
}

// round 5
// speedup vs baseline: 6.2266x; 1.8570x over previous
#include <cuda_runtime.h>
#include <cuda_fp16.h>
#include <math.h>

// ---------------------------------------------------------------------------
// NanoGPT forward (B=4, T=1024, E=1024, H=16, L=6, V=50257)
// R5: fp16-operand mma.m16n8k16 (fp32 accum) for all GEMMs + flash attention.
// Weights pre-converted to fp16 each launch; residual stream stays fp32.
// ---------------------------------------------------------------------------

#define NB     4
#define NT     1024
#define NE     1024
#define NH     16
#define HDIM   64
#define NLAYER 6
#define NV     50257
#define NM     (NB * NT)
#define LN_EPS 1e-5f

// ------------------------------- scratch -----------------------------------
__device__ float  g_x  [NM * NE];                  // residual (fp32)
__device__ __half g_h  [NM * NE];                  // LN out (fp16)
__device__ __half g_qkv[NM * 3 * NE];              // qkv (fp16)
__device__ __half g_y  [NM * NE];                  // attn out (fp16)
__device__ __half g_fc [NM * 4 * NE];              // mlp hidden (fp16)
__device__ float  g_att[(size_t)1024 * NV];        // logits chunk (fallback)
__device__ float  g_nll[NM];

// fp16 weight copies
__device__ __half w_attn[(size_t)NLAYER * 3 * NE * NE];
__device__ __half w_proj[(size_t)NLAYER * NE * NE];
__device__ __half w_fc  [(size_t)NLAYER * 4 * NE * NE];
__device__ __half w_fcp [(size_t)NLAYER * NE * 4 * NE];
__device__ __half w_lm  [(size_t)NV * NE];

// --------------------------- f32 -> f16 convert ------------------------------
__global__ void f2h_kernel(const float4* __restrict__ src,
                           __half2* __restrict__ dst, int n4) {
    int i = blockIdx.x * blockDim.x + threadIdx.x;
    if (i < n4) {
        float4 v = src[i];
        dst[2 * i]     = __floats2half2_rn(v.x, v.y);
        dst[2 * i + 1] = __floats2half2_rn(v.z, v.w);
    }
}

// ------------------------------- embed -------------------------------------
__global__ void embed_kernel(const int* __restrict__ idx,
                             const float* __restrict__ wte,
                             const float* __restrict__ wpe) {
    int row = blockIdx.x;
    int t   = row % NT;
    int tok = idx[row];
    const float* s = wte + (size_t)tok * NE;
    const float* p = wpe + (size_t)t * NE;
    float* o = g_x + (size_t)row * NE;
    for (int c = threadIdx.x; c < NE; c += blockDim.x)
        o[c] = s[c] + p[c];
}

// ------------------------------ layernorm -----------------------------------
__global__ void ln_kernel(const float* __restrict__ in,
                          const float* __restrict__ w,
                          const float* __restrict__ b,
                          __half* __restrict__ out) {
    int row = blockIdx.x;
    int tid = threadIdx.x;
    const float* x = in + (size_t)row * NE;
    __half* o = out + (size_t)row * NE;
    __shared__ float red[256];
    __shared__ float s_mu, s_rstd;

    float s = 0.f;
    for (int c = tid; c < NE; c += 256) s += x[c];
    red[tid] = s; __syncthreads();
    for (int o2 = 128; o2 > 0; o2 >>= 1) {
        if (tid < o2) red[tid] += red[tid + o2];
        __syncthreads();
    }
    if (tid == 0) s_mu = red[0] * (1.0f / NE);
    __syncthreads();
    float mu = s_mu;

    float v = 0.f;
    for (int c = tid; c < NE; c += 256) { float d = x[c] - mu; v += d * d; }
    red[tid] = v; __syncthreads();
    for (int o2 = 128; o2 > 0; o2 >>= 1) {
        if (tid < o2) red[tid] += red[tid + o2];
        __syncthreads();
    }
    if (tid == 0) s_rstd = rsqrtf(red[0] * (1.0f / NE) + LN_EPS);
    __syncthreads();
    float rstd = s_rstd;

    for (int c = tid; c < NE; c += 256)
        o[c] = __float2half((x[c] - mu) * rstd * w[c] + b[c]);
}

// ----------------------------- mma helpers ----------------------------------
__device__ __forceinline__ void mma16(float* c, const unsigned* a, const unsigned* b) {
    asm volatile(
        "mma.sync.aligned.m16n8k16.row.col.f32.f16.f16.f32 "
        "{%0,%1,%2,%3}, {%4,%5,%6,%7}, {%8,%9}, {%0,%1,%2,%3};"
        : "+f"(c[0]), "+f"(c[1]), "+f"(c[2]), "+f"(c[3])
        : "r"(a[0]), "r"(a[1]), "r"(a[2]), "r"(a[3]),
          "r"(b[0]), "r"(b[1]));
}

__device__ __forceinline__ void cpa16(void* dst, const void* src, bool full) {
    unsigned d = (unsigned)__cvta_generic_to_shared(dst);
    int sz = full ? 16 : 0;
    asm volatile("cp.async.cg.shared.global [%0], [%1], 16, %2;"
                 :: "r"(d), "l"(src), "r"(sz));
}

__device__ __forceinline__ unsigned lds_u32(const __half* p) {
    return *(const unsigned*)p;
}

__device__ __forceinline__ float gelu_f(float x) {
    return 0.5f * x * (1.0f + erff(x * 0.70710678118654752f));
}

// ------------------------- fp16 tensor-core GEMM -----------------------------
// C[M,N] = A[M,K] * B^T (A,B fp16; accum f32). Block 128x128, BK=32, 4 stages.
// EPI: 0 f32 store (guarded), 1 f16 store, 2 gelu->f16, 3 f32 += (N%128==0 for 1-3)
#define STAGES 4
#define SPAD   40                         // halves per smem row (32 + 8)
#define STG_H  (2 * 128 * SPAD)           // halves per stage

template <int EPI>
__global__ void __launch_bounds__(256, 2)
mma_gemm(const __half* __restrict__ A, const __half* __restrict__ B,
         void* __restrict__ Cv,
         int M, int N, int K, int lda, int ldb, int ldc) {
    extern __shared__ __half sh[];
    const int bm   = blockIdx.y * 128;
    const int bn   = blockIdx.x * 128;
    const int tid  = threadIdx.x;
    const int lane = tid & 31;
    const int wid  = tid >> 5;
    const int wm   = (wid >> 2) * 64;
    const int wn   = (wid & 3) * 32;
    const int lr   = lane >> 2;
    const int lc   = lane & 3;

    // 512 16B-chunks per operand tile; 2 per thread
    const int r0c = tid >> 2,          c0c = (tid & 3) * 8;
    const int r1c = (tid + 256) >> 2,  c1c = ((tid + 256) & 3) * 8;

    const __half* Ar0 = A + (size_t)(bm + r0c) * lda + c0c;
    const __half* Ar1 = A + (size_t)(bm + r1c) * lda + c1c;
    const bool bv0 = (bn + r0c) < N;
    const bool bv1 = (bn + r1c) < N;
    const __half* Br0 = B + (size_t)min(bn + r0c, N - 1) * ldb + c0c;
    const __half* Br1 = B + (size_t)min(bn + r1c, N - 1) * ldb + c1c;

    float acc[4][4][4];
#pragma unroll
    for (int i = 0; i < 4; i++)
#pragma unroll
        for (int j = 0; j < 4; j++)
#pragma unroll
            for (int q = 0; q < 4; q++) acc[i][j][q] = 0.f;

    const int KT = K / 32;

#pragma unroll
    for (int s = 0; s < STAGES - 1; s++) {
        __half* sA = sh + s * STG_H;
        __half* sB = sA + 128 * SPAD;
        int k0 = s * 32;
        cpa16(sA + r0c * SPAD + c0c, Ar0 + k0, true);
        cpa16(sA + r1c * SPAD + c1c, Ar1 + k0, true);
        cpa16(sB + r0c * SPAD + c0c, Br0 + k0, bv0);
        cpa16(sB + r1c * SPAD + c1c, Br1 + k0, bv1);
        asm volatile("cp.async.commit_group;");
    }

    for (int kt = 0; kt < KT; kt++) {
        asm volatile("cp.async.wait_group %0;" :: "n"(STAGES - 2));
        __syncthreads();

        int pf = kt + STAGES - 1;
        if (pf < KT) {
            __half* sA = sh + (pf % STAGES) * STG_H;
            __half* sB = sA + 128 * SPAD;
            int k0 = pf * 32;
            cpa16(sA + r0c * SPAD + c0c, Ar0 + k0, true);
            cpa16(sA + r1c * SPAD + c1c, Ar1 + k0, true);
            cpa16(sB + r0c * SPAD + c0c, Br0 + k0, bv0);
            cpa16(sB + r1c * SPAD + c1c, Br1 + k0, bv1);
        }
        asm volatile("cp.async.commit_group;");

        const __half* As = sh + (kt % STAGES) * STG_H;
        const __half* Bs = As + 128 * SPAD;
#pragma unroll
        for (int ks = 0; ks < 2; ks++) {
            const int k0 = ks * 16 + 2 * lc;
            unsigned afr[4][4], bfr[4][2];
#pragma unroll
            for (int i = 0; i < 4; i++) {
                const __half* p = &As[(wm + i * 16 + lr) * SPAD + k0];
                afr[i][0] = lds_u32(p);
                afr[i][1] = lds_u32(p + 8 * SPAD);
                afr[i][2] = lds_u32(p + 8);
                afr[i][3] = lds_u32(p + 8 * SPAD + 8);
            }
#pragma unroll
            for (int j = 0; j < 4; j++) {
                const __half* p = &Bs[(wn + j * 8 + lr) * SPAD + k0];
                bfr[j][0] = lds_u32(p);
                bfr[j][1] = lds_u32(p + 8);
            }
#pragma unroll
            for (int i = 0; i < 4; i++)
#pragma unroll
                for (int j = 0; j < 4; j++)
                    mma16(acc[i][j], afr[i], bfr[j]);
        }
        __syncthreads();
    }

    // ---- epilogue ----
#pragma unroll
    for (int i = 0; i < 4; i++) {
        int r0 = bm + wm + i * 16 + lr;
#pragma unroll
        for (int j = 0; j < 4; j++) {
            int c0 = bn + wn + j * 8 + (lc << 1);
            const float* a4 = acc[i][j];
            if (EPI == 0) {
                float* C0 = (float*)Cv + (size_t)r0 * ldc;
                float* C1 = C0 + (size_t)8 * ldc;
#pragma unroll
                for (int q = 0; q < 2; q++) {
                    int col = c0 + q;
                    if (col < N) { C0[col] = a4[q]; C1[col] = a4[q + 2]; }
                }
            } else if (EPI == 1) {
                __half* C0 = (__half*)Cv + (size_t)r0 * ldc;
                __half* C1 = C0 + (size_t)8 * ldc;
                *(__half2*)&C0[c0] = __floats2half2_rn(a4[0], a4[1]);
                *(__half2*)&C1[c0] = __floats2half2_rn(a4[2], a4[3]);
            } else if (EPI == 2) {
                __half* C0 = (__half*)Cv + (size_t)r0 * ldc;
                __half* C1 = C0 + (size_t)8 * ldc;
                *(__half2*)&C0[c0] = __floats2half2_rn(gelu_f(a4[0]), gelu_f(a4[1]));
                *(__half2*)&C1[c0] = __floats2half2_rn(gelu_f(a4[2]), gelu_f(a4[3]));
            } else {
                float* C0 = (float*)Cv + (size_t)r0 * ldc;
                float* C1 = C0 + (size_t)8 * ldc;
                C0[c0] += a4[0]; C0[c0 + 1] += a4[1];
                C1[c0] += a4[2]; C1[c0 + 1] += a4[3];
            }
        }
    }
}

// --------------------------- flash attention ---------------------------------
// CTA: 128 q-rows of one (b,h); 8 warps x 16 q-rows; kv-tiles of 64; fp16 mma.
// P stays in registers (lane-exact frag reuse). V transposed to smem.
#define QP 72
#define VP 74
#define FA_SMEM ((64 * QP + 64 * VP) * (int)sizeof(__half))

__global__ void __launch_bounds__(256, 2)
flash_attn_kernel() {
    extern __shared__ __half fsh[];
    __half* sK  = fsh;                  // [64][QP]
    __half* sVt = fsh + 64 * QP;        // [64 hd][VP seq]

    const int qt  = blockIdx.x;
    const int bh  = blockIdx.y;
    const int b   = bh >> 4, h = bh & 15;
    const int tid = threadIdx.x;
    const int w   = tid >> 5;
    const int lane = tid & 31;
    const int lr  = lane >> 2;
    const int lc  = lane & 3;
    const int wrow = w * 16 + lr;

    const __half* base = g_qkv + (size_t)b * NT * 3 * NE + h * 64;

    // ---- stage Q (128 x 64) into fsh (stride QP), extract frags ----
    {
        const __half* Qg = base + (size_t)(qt * 128) * 3 * NE;
#pragma unroll
        for (int i = 0; i < 4; i++) {
            int idx = tid + i * 256;
            int row = idx >> 3, col = (idx & 7) * 8;
            cpa16(fsh + row * QP + col, Qg + (size_t)row * 3 * NE + col, true);
        }
        asm volatile("cp.async.commit_group;");
        asm volatile("cp.async.wait_group 0;");
        __syncthreads();
    }

    unsigned qf[4][4];
#pragma unroll
    for (int ks = 0; ks < 4; ks++) {
        const __half* p = &fsh[wrow * QP + ks * 16 + 2 * lc];
        qf[ks][0] = lds_u32(p);
        qf[ks][1] = lds_u32(p + 8 * QP);
        qf[ks][2] = lds_u32(p + 8);
        qf[ks][3] = lds_u32(p + 8 * QP + 8);
    }
    __syncthreads();

    float oacc[8][4];
#pragma unroll
    for (int j = 0; j < 8; j++)
#pragma unroll
        for (int q = 0; q < 4; q++) oacc[j][q] = 0.f;
    float m0 = -1e30f, m1 = -1e30f, l0 = 0.f, l1 = 0.f;

    const int row0 = qt * 128 + wrow;
    const int row1 = row0 + 8;
    const int ntiles = 2 * qt + 2;

    // V-transpose thread mapping: 2 seq rows x 8 hd per thread
    const int sp  = tid >> 3;           // 0..31 (seq pair)
    const int hd0 = (tid & 7) * 8;      // 0..56

    for (int j = 0; j < ntiles; j++) {
        // K tile via cp.async
        const __half* Kg = base + NE + (size_t)(j * 64) * 3 * NE;
#pragma unroll
        for (int i = 0; i < 2; i++) {
            int idx = tid + i * 256;
            int row = idx >> 3, col = (idx & 7) * 8;
            cpa16(sK + row * QP + col, Kg + (size_t)row * 3 * NE + col, true);
        }
        asm volatile("cp.async.commit_group;");

        // V tile: direct load + transpose into sVt[hd][seq]
        {
            const __half* v0 = base + 2 * NE + (size_t)(j * 64 + 2 * sp) * 3 * NE + hd0;
            const __half* v1 = v0 + 3 * NE;
            uint4 u0 = *(const uint4*)v0;
            uint4 u1 = *(const uint4*)v1;
            __half ha[8], hb[8];
            *(uint4*)ha = u0; *(uint4*)hb = u1;
#pragma unroll
            for (int q = 0; q < 8; q++)
                *(__half2*)&sVt[(hd0 + q) * VP + 2 * sp] = __halves2half2(ha[q], hb[q]);
        }
        asm volatile("cp.async.wait_group 0;");
        __syncthreads();

        // ---- S = Q K^T ----
        float sacc[8][4];
#pragma unroll
        for (int jn = 0; jn < 8; jn++)
#pragma unroll
            for (int q = 0; q < 4; q++) sacc[jn][q] = 0.f;
#pragma unroll
        for (int ks = 0; ks < 4; ks++) {
            const int k0 = ks * 16 + 2 * lc;
#pragma unroll
            for (int jn = 0; jn < 8; jn++) {
                unsigned bf[2];
                const __half* p = &sK[(jn * 8 + lr) * QP + k0];
                bf[0] = lds_u32(p);
                bf[1] = lds_u32(p + 8);
                mma16(sacc[jn], qf[ks], bf);
            }
        }

        // ---- mask + scale + tile max ----
        const float sc = 0.125f;
        float tm0 = -1e30f, tm1 = -1e30f;
#pragma unroll
        for (int jn = 0; jn < 8; jn++) {
            int col = j * 64 + jn * 8 + (lc << 1);
            sacc[jn][0] = (col     <= row0) ? sacc[jn][0] * sc : -1e30f;
            sacc[jn][1] = (col + 1 <= row0) ? sacc[jn][1] * sc : -1e30f;
            sacc[jn][2] = (col     <= row1) ? sacc[jn][2] * sc : -1e30f;
            sacc[jn][3] = (col + 1 <= row1) ? sacc[jn][3] * sc : -1e30f;
            tm0 = fmaxf(tm0, fmaxf(sacc[jn][0], sacc[jn][1]));
            tm1 = fmaxf(tm1, fmaxf(sacc[jn][2], sacc[jn][3]));
        }
        tm0 = fmaxf(tm0, __shfl_xor_sync(0xffffffffu, tm0, 1));
        tm0 = fmaxf(tm0, __shfl_xor_sync(0xffffffffu, tm0, 2));
        tm1 = fmaxf(tm1, __shfl_xor_sync(0xffffffffu, tm1, 1));
        tm1 = fmaxf(tm1, __shfl_xor_sync(0xffffffffu, tm1, 2));

        float mn0 = fmaxf(m0, tm0), mn1 = fmaxf(m1, tm1);
        float a0 = __expf(m0 - mn0), a1 = __expf(m1 - mn1);
        m0 = mn0; m1 = mn1;

        // ---- exp in f32 (kept in sacc), row sums ----
        float rs0 = 0.f, rs1 = 0.f;
#pragma unroll
        for (int jn = 0; jn < 8; jn++) {
            sacc[jn][0] = __expf(sacc[jn][0] - m0);
            sacc[jn][1] = __expf(sacc[jn][1] - m0);
            sacc[jn][2] = __expf(sacc[jn][2] - m1);
            sacc[jn][3] = __expf(sacc[jn][3] - m1);
            rs0 += sacc[jn][0] + sacc[jn][1];
            rs1 += sacc[jn][2] + sacc[jn][3];
        }
        rs0 += __shfl_xor_sync(0xffffffffu, rs0, 1);
        rs0 += __shfl_xor_sync(0xffffffffu, rs0, 2);
        rs1 += __shfl_xor_sync(0xffffffffu, rs1, 1);
        rs1 += __shfl_xor_sync(0xffffffffu, rs1, 2);
        l0 = l0 * a0 + rs0;
        l1 = l1 * a1 + rs1;
#pragma unroll
        for (int jo = 0; jo < 8; jo++) {
            oacc[jo][0] *= a0; oacc[jo][1] *= a0;
            oacc[jo][2] *= a1; oacc[jo][3] *= a1;
        }

        // ---- O += P V  (P packed from registers — lane-exact frag match) ----
#pragma unroll
        for (int ks = 0; ks < 4; ks++) {
            unsigned af[4];
            {
                __half2 t;
                t = __floats2half2_rn(sacc[2 * ks][0],     sacc[2 * ks][1]);     af[0] = *(unsigned*)&t;
                t = __floats2half2_rn(sacc[2 * ks][2],     sacc[2 * ks][3]);     af[1] = *(unsigned*)&t;
                t = __floats2half2_rn(sacc[2 * ks + 1][0], sacc[2 * ks + 1][1]); af[2] = *(unsigned*)&t;
                t = __floats2half2_rn(sacc[2 * ks + 1][2], sacc[2 * ks + 1][3]); af[3] = *(unsigned*)&t;
            }
            const int k0 = ks * 16 + 2 * lc;
#pragma unroll
            for (int jo = 0; jo < 8; jo++) {
                unsigned bf[2];
                const __half* p = &sVt[(jo * 8 + lr) * VP + k0];
                bf[0] = lds_u32(p);
                bf[1] = lds_u32(p + 8);
                mma16(oacc[jo], af, bf);
            }
        }
        __syncthreads();
    }

    // ---- finalize ----
    float inv0 = 1.0f / l0, inv1 = 1.0f / l1;
    __half* y0 = g_y + ((size_t)b * NT + row0) * NE + h * 64;
    __half* y1 = y0 + (size_t)8 * NE;
#pragma unroll
    for (int jo = 0; jo < 8; jo++) {
        int col = jo * 8 + (lc << 1);
        *(__half2*)&y0[col] = __floats2half2_rn(oacc[jo][0] * inv0, oacc[jo][1] * inv0);
        *(__half2*)&y1[col] = __floats2half2_rn(oacc[jo][2] * inv1, oacc[jo][3] * inv1);
    }
}

// ------------------------------- loss ---------------------------------------
__global__ void loss_row_kernel(const float* __restrict__ logits,
                                const int* __restrict__ targets,
                                int row0, int ldl) {
    int r = blockIdx.x;
    int tid = threadIdx.x;
    const float* L = logits + (size_t)r * ldl;
    float m = -1e30f, sacc = 0.f;
    for (int j = tid; j < NV; j += 256) {
        float v = L[j];
        if (v > m) { sacc = sacc * expf(m - v) + 1.0f; m = v; }
        else       { sacc += expf(v - m); }
    }
    __shared__ float sm[256], ss[256];
    sm[tid] = m; ss[tid] = sacc; __syncthreads();
    for (int o = 128; o > 0; o >>= 1) {
        if (tid < o) {
            float m2 = sm[tid + o], s2 = ss[tid + o];
            float M  = fmaxf(sm[tid], m2);
            ss[tid]  = ss[tid] * expf(sm[tid] - M) + s2 * expf(m2 - M);
            sm[tid]  = M;
        }
        __syncthreads();
    }
    if (tid == 0) {
        int grow = row0 + r;
        int tgt = targets[grow];
        float nll = 0.f;
        if (tgt != -1) nll = sm[0] + logf(ss[0]) - L[tgt];
        g_nll[grow] = nll;
    }
}

__global__ void loss_reduce_kernel(const int* __restrict__ targets,
                                   float* __restrict__ out) {
    int tid = threadIdx.x;
    __shared__ float ssum[256];
    __shared__ int scnt[256];
    float s = 0.f; int c = 0;
    for (int r = tid; r < NM; r += 256)
        if (targets[r] != -1) { s += g_nll[r]; c++; }
    ssum[tid] = s; scnt[tid] = c; __syncthreads();
    for (int o = 128; o > 0; o >>= 1) {
        if (tid < o) { ssum[tid] += ssum[tid + o]; scnt[tid] += scnt[tid + o]; }
        __syncthreads();
    }
    if (tid == 0) out[0] = ssum[0] / (float)max(scnt[0], 1);
}

// ------------------------------- host ---------------------------------------
static const int MMA_SMEM = STAGES * STG_H * (int)sizeof(__half);   // 81920 B

template <int EPI>
static void launch_mma(const __half* A, const __half* B, void* C,
                       int M, int N, int K, int lda, int ldb, int ldc) {
    dim3 grid((N + 127) / 128, M / 128);
    mma_gemm<EPI><<<grid, 256, MMA_SMEM>>>(A, B, C, M, N, K, lda, ldb, ldc);
}

static void conv_f2h(const float* s, __half* d, size_t n) {
    int n4 = (int)(n / 4);
    f2h_kernel<<<(n4 + 255) / 256, 256>>>((const float4*)s, (__half2*)d, n4);
}

extern "C" void kernel_launch(void* const* d_in, const int* in_sizes, int n_in,
                              void* d_out, int out_size) {
    const int*   idx      = (const int*)  d_in[0];
    const int*   targets  = (const int*)  d_in[1];
    const float* wte      = (const float*)d_in[2];
    const float* wpe      = (const float*)d_in[3];
    const float* ln1_w    = (const float*)d_in[4];
    const float* ln1_b    = (const float*)d_in[5];
    const float* attn_w   = (const float*)d_in[6];
    const float* attn_pw  = (const float*)d_in[7];
    const float* ln2_w    = (const float*)d_in[8];
    const float* ln2_b    = (const float*)d_in[9];
    const float* fc_w     = (const float*)d_in[10];
    const float* fc_pw    = (const float*)d_in[11];
    const float* lnf_w    = (const float*)d_in[12];
    const float* lnf_b    = (const float*)d_in[13];
    const float* lm_w     = (const float*)d_in[14];

    cudaFuncSetAttribute(mma_gemm<0>, cudaFuncAttributeMaxDynamicSharedMemorySize, MMA_SMEM);
    cudaFuncSetAttribute(mma_gemm<1>, cudaFuncAttributeMaxDynamicSharedMemorySize, MMA_SMEM);
    cudaFuncSetAttribute(mma_gemm<2>, cudaFuncAttributeMaxDynamicSharedMemorySize, MMA_SMEM);
    cudaFuncSetAttribute(mma_gemm<3>, cudaFuncAttributeMaxDynamicSharedMemorySize, MMA_SMEM);
    cudaFuncSetAttribute(flash_attn_kernel, cudaFuncAttributeMaxDynamicSharedMemorySize, FA_SMEM);

    float *x, *att;
    __half *h, *qkv, *y, *fc;
    __half *wa, *wp, *wf, *wfp, *wl;
    cudaGetSymbolAddress((void**)&x,   g_x);
    cudaGetSymbolAddress((void**)&h,   g_h);
    cudaGetSymbolAddress((void**)&qkv, g_qkv);
    cudaGetSymbolAddress((void**)&y,   g_y);
    cudaGetSymbolAddress((void**)&fc,  g_fc);
    cudaGetSymbolAddress((void**)&att, g_att);
    cudaGetSymbolAddress((void**)&wa,  w_attn);
    cudaGetSymbolAddress((void**)&wp,  w_proj);
    cudaGetSymbolAddress((void**)&wf,  w_fc);
    cudaGetSymbolAddress((void**)&wfp, w_fcp);
    cudaGetSymbolAddress((void**)&wl,  w_lm);

    // weight conversion (every launch; deterministic)
    conv_f2h(attn_w,  wa,  (size_t)NLAYER * 3 * NE * NE);
    conv_f2h(attn_pw, wp,  (size_t)NLAYER * NE * NE);
    conv_f2h(fc_w,    wf,  (size_t)NLAYER * 4 * NE * NE);
    conv_f2h(fc_pw,   wfp, (size_t)NLAYER * NE * 4 * NE);
    conv_f2h(lm_w,    wl,  (size_t)NV * NE);

    embed_kernel<<<NM, 256>>>(idx, wte, wpe);

    for (int i = 0; i < NLAYER; i++) {
        const __half* aw  = wa  + (size_t)i * 3 * NE * NE;
        const __half* pw  = wp  + (size_t)i * NE * NE;
        const __half* fw  = wf  + (size_t)i * 4 * NE * NE;
        const __half* fpw = wfp + (size_t)i * NE * 4 * NE;

        ln_kernel<<<NM, 256>>>(x, ln1_w + i * NE, ln1_b + i * NE, h);
        launch_mma<1>(h, aw, qkv, NM, 3 * NE, NE, NE, NE, 3 * NE);
        flash_attn_kernel<<<dim3(NT / 128, NB * NH), 256, FA_SMEM>>>();
        launch_mma<3>(y, pw, x, NM, NE, NE, NE, NE, NE);
        ln_kernel<<<NM, 256>>>(x, ln2_w + i * NE, ln2_b + i * NE, h);
        launch_mma<2>(h, fw, fc, NM, 4 * NE, NE, NE, NE, 4 * NE);
        launch_mma<3>(fc, fpw, x, NM, NE, 4 * NE, 4 * NE, 4 * NE, NE);
    }

    ln_kernel<<<NM, 256>>>(x, lnf_w, lnf_b, h);

    const size_t P = (size_t)NM * NV;
    float* out = (float*)d_out;

    if ((size_t)out_size >= P) {
        launch_mma<0>(h, wl, out, NM, NV, NE, NE, NE, NV);
        loss_row_kernel<<<NM, 256>>>(out, targets, 0, NV);
        if ((size_t)out_size >= P + 1)
            loss_reduce_kernel<<<1, 256>>>(targets, out + P);
    } else {
        const int CHUNK = 1024;
        for (int c = 0; c < NM / CHUNK; c++) {
            launch_mma<0>(h + (size_t)c * CHUNK * NE, wl, att,
                          CHUNK, NV, NE, NE, NE, NV);
            loss_row_kernel<<<CHUNK, 256>>>(att, targets, c * CHUNK, NV);
        }
        int li = (out_size >= 1) ? out_size - 1 : 0;
        loss_reduce_kernel<<<1, 256>>>(targets, out + li);
    }
}